// round 2
// baseline (speedup 1.0000x reference)
#include <cuda_runtime.h>

namespace {
constexpr int Bb = 8;
constexpr int Ss = 2048;
constexpr int Dd = 128;
constexpr int BM = 128;   // query rows per CTA
constexpr int BN = 64;    // keys per tile
constexpr int NT = 256;   // threads per CTA (16x16)
constexpr int PP = BN + 4; // Ps pitch (floats)

// smem layout (floats)
constexpr int OFF_Q = 0;                    // Qs[D][BM]
constexpr int OFF_K = OFF_Q + Dd * BM;      // Ks[D][BN]
constexpr int OFF_V = OFF_K + Dd * BN;      // Vs[BN][D]
constexpr int OFF_P = OFF_V + BN * Dd;      // Ps[BM][PP]
constexpr int SMEM_FLOATS = OFF_P + BM * PP;
}

// Normalized mask scratch (allocation-free per the rules) + detected mode.
__device__ unsigned char g_mask_bytes[Bb * Ss];
__device__ int g_mask_mode; // 0 = 1-byte, 1 = bf16 (2-byte), 2 = 4-byte (int32/fp32)

// ---- Kernel 1: detect mask element width by scanning the first 16 KB ----
__global__ void detect_mask_mode_kernel(const unsigned int* __restrict__ M)
{
    __shared__ int ok4, ok2;
    if (threadIdx.x == 0) { ok4 = 1; ok2 = 1; }
    __syncthreads();

    int bad4 = 0, bad2 = 0;
    for (int i = threadIdx.x; i < 4096; i += blockDim.x) {
        unsigned int w = M[i];
        // 4-byte candidates: int32 {0,1} or fp32 {0, 1.0f}
        if (!(w == 0u || w == 1u || w == 0x3F800000u)) bad4 = 1;
        // bf16 candidates: halves in {0x0000, 0x3F80}
        unsigned int lo = w & 0xFFFFu, hi = w >> 16;
        if (!((lo == 0u || lo == 0x3F80u) && (hi == 0u || hi == 0x3F80u))) bad2 = 1;
    }
    if (bad4) atomicAnd(&ok4, 0);
    if (bad2) atomicAnd(&ok2, 0);
    __syncthreads();
    if (threadIdx.x == 0) g_mask_mode = ok4 ? 2 : (ok2 ? 1 : 0);
}

// ---- Kernel 2: normalize mask to bytes ----
__global__ void convert_mask_kernel(const void* __restrict__ M)
{
    int i = blockIdx.x * blockDim.x + threadIdx.x;
    if (i >= Bb * Ss) return;
    int mode = g_mask_mode;
    unsigned char masked;
    if (mode == 2)      masked = (((const unsigned int*)M)[i]   != 0u);
    else if (mode == 1) masked = (((const unsigned short*)M)[i] != 0u);
    else                masked = (((const unsigned char*)M)[i]  != 0u);
    g_mask_bytes[i] = masked;
}

// ---- Kernel 3: flash attention forward ----
__global__ void __launch_bounds__(NT, 1)
attn_fwd_kernel(const float* __restrict__ Qg, const float* __restrict__ Kg,
                const float* __restrict__ Vg, float* __restrict__ Og)
{
    extern __shared__ float smem[];
    float* Qs = smem + OFF_Q;
    float* Ks = smem + OFF_K;
    float* Vs = smem + OFF_V;
    float* Ps = smem + OFF_P;

    const int b    = blockIdx.y;
    const int m0   = blockIdx.x * BM;
    const int tid  = threadIdx.x;
    const int tx   = tid & 15;   // key cols / out cols
    const int ty   = tid >> 4;   // query rows
    const int lane = tid & 31;
    const int warp = tid >> 5;

    const float* Qb = Qg + (size_t)b * Ss * Dd;
    const float* Kb = Kg + (size_t)b * Ss * Dd;
    const float* Vb = Vg + (size_t)b * Ss * Dd;
    const unsigned char* Mb = g_mask_bytes + (size_t)b * Ss;

    // ---- Load Q tile transposed into Qs[d][r] (conflict-free STS) ----
    #pragma unroll
    for (int it = 0; it < 16; ++it) {
        int chunk = it * 8 + warp;     // 0..127 -> (rb 0..3, d4 0..31)
        int d4 = chunk & 31;
        int rb = chunk >> 5;
        int r  = rb * 32 + lane;
        float4 q = *reinterpret_cast<const float4*>(Qb + (size_t)(m0 + r) * Dd + 4 * d4);
        Qs[(4 * d4 + 0) * BM + r] = q.x;
        Qs[(4 * d4 + 1) * BM + r] = q.y;
        Qs[(4 * d4 + 2) * BM + r] = q.z;
        Qs[(4 * d4 + 3) * BM + r] = q.w;
    }

    float o[8][8];
    float mrow[8], lrow[8];
    #pragma unroll
    for (int i = 0; i < 8; ++i) {
        mrow[i] = -1e30f;
        lrow[i] = 0.0f;
        #pragma unroll
        for (int j = 0; j < 8; ++j) o[i][j] = 0.0f;
    }

    const float inv_scale = 0.08838834764831845f; // 1/sqrt(128)

    for (int n0 = 0; n0 < Ss; n0 += BN) {
        __syncthreads();

        // ---- K tile transposed: Ks[d][r] ----
        #pragma unroll
        for (int it = 0; it < 8; ++it) {
            int chunk = it * 8 + warp;   // 0..63 -> (rb 0..1, d4 0..31)
            int d4 = chunk & 31;
            int rb = chunk >> 5;
            int r  = rb * 32 + lane;
            float4 k = *reinterpret_cast<const float4*>(Kb + (size_t)(n0 + r) * Dd + 4 * d4);
            Ks[(4 * d4 + 0) * BN + r] = k.x;
            Ks[(4 * d4 + 1) * BN + r] = k.y;
            Ks[(4 * d4 + 2) * BN + r] = k.z;
            Ks[(4 * d4 + 3) * BN + r] = k.w;
        }
        // ---- V tile: coalesced copy ----
        #pragma unroll
        for (int it = 0; it < 8; ++it) {
            int f  = it * NT + tid;
            int n  = f >> 5;
            int d4 = f & 31;
            float4 v = *reinterpret_cast<const float4*>(Vb + (size_t)(n0 + n) * Dd + 4 * d4);
            *reinterpret_cast<float4*>(Vs + n * Dd + 4 * d4) = v;
        }
        // mask bytes for this thread's 4 keys
        uchar4 mk = *reinterpret_cast<const uchar4*>(Mb + n0 + 4 * tx);

        __syncthreads();

        // ---- S = Q K^T ----
        float s[8][4];
        #pragma unroll
        for (int i = 0; i < 8; ++i)
            #pragma unroll
            for (int j = 0; j < 4; ++j) s[i][j] = 0.0f;

        #pragma unroll 4
        for (int d = 0; d < Dd; ++d) {
            float4 q0 = *reinterpret_cast<const float4*>(Qs + d * BM + 8 * ty);
            float4 q1 = *reinterpret_cast<const float4*>(Qs + d * BM + 8 * ty + 4);
            float4 kf = *reinterpret_cast<const float4*>(Ks + d * BN + 4 * tx);
            float qa[8] = {q0.x, q0.y, q0.z, q0.w, q1.x, q1.y, q1.z, q1.w};
            float ka[4] = {kf.x, kf.y, kf.z, kf.w};
            #pragma unroll
            for (int i = 0; i < 8; ++i)
                #pragma unroll
                for (int j = 0; j < 4; ++j)
                    s[i][j] = fmaf(qa[i], ka[j], s[i][j]);
        }

        // ---- scale + mask + online softmax ----
        const bool mj[4] = {mk.x != 0, mk.y != 0, mk.z != 0, mk.w != 0};
        #pragma unroll
        for (int i = 0; i < 8; ++i) {
            float tm = -1e30f;
            #pragma unroll
            for (int j = 0; j < 4; ++j) {
                float v = s[i][j] * inv_scale;
                if (mj[j]) v = -1e30f;
                s[i][j] = v;
                tm = fmaxf(tm, v);
            }
            tm = fmaxf(tm, __shfl_xor_sync(0xffffffffu, tm, 1));
            tm = fmaxf(tm, __shfl_xor_sync(0xffffffffu, tm, 2));
            tm = fmaxf(tm, __shfl_xor_sync(0xffffffffu, tm, 4));
            tm = fmaxf(tm, __shfl_xor_sync(0xffffffffu, tm, 8));

            float mnew  = fmaxf(mrow[i], tm);
            float alpha = __expf(mrow[i] - mnew);
            mrow[i] = mnew;

            float ps = 0.0f;
            #pragma unroll
            for (int j = 0; j < 4; ++j) {
                float p = __expf(s[i][j] - mnew);
                s[i][j] = p;
                ps += p;
            }
            ps += __shfl_xor_sync(0xffffffffu, ps, 1);
            ps += __shfl_xor_sync(0xffffffffu, ps, 2);
            ps += __shfl_xor_sync(0xffffffffu, ps, 4);
            ps += __shfl_xor_sync(0xffffffffu, ps, 8);

            lrow[i] = lrow[i] * alpha + ps;
            #pragma unroll
            for (int c = 0; c < 8; ++c) o[i][c] *= alpha;
        }

        // ---- store P tile ----
        #pragma unroll
        for (int i = 0; i < 8; ++i) {
            float4 pv = make_float4(s[i][0], s[i][1], s[i][2], s[i][3]);
            *reinterpret_cast<float4*>(Ps + (8 * ty + i) * PP + 4 * tx) = pv;
        }
        __syncthreads();

        // ---- O += P @ V ----
        #pragma unroll 2
        for (int j = 0; j < BN; ++j) {
            float4 v0 = *reinterpret_cast<const float4*>(Vs + j * Dd + 8 * tx);
            float4 v1 = *reinterpret_cast<const float4*>(Vs + j * Dd + 8 * tx + 4);
            float va[8] = {v0.x, v0.y, v0.z, v0.w, v1.x, v1.y, v1.z, v1.w};
            float pr[8];
            #pragma unroll
            for (int i = 0; i < 8; ++i) pr[i] = Ps[(8 * ty + i) * PP + j];
            #pragma unroll
            for (int i = 0; i < 8; ++i)
                #pragma unroll
                for (int c = 0; c < 8; ++c)
                    o[i][c] = fmaf(pr[i], va[c], o[i][c]);
        }
    }

    // ---- epilogue ----
    #pragma unroll
    for (int i = 0; i < 8; ++i) {
        float inv_l = 1.0f / lrow[i];
        size_t row = (size_t)b * Ss + (m0 + 8 * ty + i);
        float4 a0 = make_float4(o[i][0] * inv_l, o[i][1] * inv_l,
                                o[i][2] * inv_l, o[i][3] * inv_l);
        float4 a1 = make_float4(o[i][4] * inv_l, o[i][5] * inv_l,
                                o[i][6] * inv_l, o[i][7] * inv_l);
        *reinterpret_cast<float4*>(Og + row * Dd + 8 * tx)     = a0;
        *reinterpret_cast<float4*>(Og + row * Dd + 8 * tx + 4) = a1;
    }
}

extern "C" void kernel_launch(void* const* d_in, const int* in_sizes, int n_in,
                              void* d_out, int out_size)
{
    const float* q = (const float*)d_in[0];
    const float* k = (const float*)d_in[1];
    const float* v = (const float*)d_in[2];
    const void*  m = d_in[3];
    float* out = (float*)d_out;

    // 1) detect mask dtype width
    detect_mask_mode_kernel<<<1, 256>>>((const unsigned int*)m);
    // 2) normalize mask to bytes
    convert_mask_kernel<<<(Bb * Ss + 255) / 256, 256>>>(m);

    // 3) attention
    size_t smem_bytes = (size_t)SMEM_FLOATS * sizeof(float);
    cudaFuncSetAttribute(attn_fwd_kernel,
                         cudaFuncAttributeMaxDynamicSharedMemorySize,
                         (int)smem_bytes);
    dim3 grid(Ss / BM, Bb);
    attn_fwd_kernel<<<grid, NT, smem_bytes>>>(q, k, v, out);
}

// round 3
// speedup vs baseline: 1.0675x; 1.0675x over previous
#include <cuda_runtime.h>

namespace {
constexpr int Bb = 8;
constexpr int Ss = 2048;
constexpr int Dd = 128;
constexpr int BM = 128;   // query rows per CTA
constexpr int BN = 64;    // keys per tile
constexpr int NT = 256;   // threads per CTA (16x16)
constexpr int PP = BN + 4; // Ps pitch (floats)

constexpr int OFF_Q = 0;                    // Qs[D][BM]
constexpr int OFF_K = OFF_Q + Dd * BM;      // Ks[D][BN]
constexpr int OFF_V = OFF_K + Dd * BN;      // Vs[BN][D]
constexpr int OFF_P = OFF_V + BN * Dd;      // Ps[BM][PP]
constexpr int SMEM_FLOATS = OFF_P + BM * PP;
}

// ---- packed f32x2 helpers (Blackwell FFMA2 path) ----
__device__ __forceinline__ void fma2(unsigned long long& d,
                                     unsigned long long a,
                                     unsigned long long b) {
    asm("fma.rn.f32x2 %0, %1, %2, %0;" : "+l"(d) : "l"(a), "l"(b));
}
__device__ __forceinline__ void mul2(unsigned long long& d,
                                     unsigned long long a) {
    asm("mul.rn.f32x2 %0, %0, %1;" : "+l"(d) : "l"(a));
}
__device__ __forceinline__ unsigned long long dup2(float x) {
    unsigned long long r;
    asm("mov.b64 %0, {%1, %1};" : "=l"(r) : "f"(x));
    return r;
}
__device__ __forceinline__ float2 unpk(unsigned long long v) {
    float2 f;
    asm("mov.b64 {%0, %1}, %2;" : "=f"(f.x), "=f"(f.y) : "l"(v));
    return f;
}

// Normalized mask scratch + detected element width.
__device__ unsigned char g_mask_bytes[Bb * Ss];
__device__ int g_mask_mode; // 0 = 1-byte, 1 = bf16, 2 = 4-byte (int32/fp32)

__global__ void detect_mask_mode_kernel(const unsigned int* __restrict__ M)
{
    __shared__ int ok4, ok2;
    if (threadIdx.x == 0) { ok4 = 1; ok2 = 1; }
    __syncthreads();
    int bad4 = 0, bad2 = 0;
    for (int i = threadIdx.x; i < 2048; i += blockDim.x) {
        unsigned int w = M[i];
        if (!(w == 0u || w == 1u || w == 0x3F800000u)) bad4 = 1;
        unsigned int lo = w & 0xFFFFu, hi = w >> 16;
        if (!((lo == 0u || lo == 0x3F80u) && (hi == 0u || hi == 0x3F80u))) bad2 = 1;
    }
    if (bad4) atomicAnd(&ok4, 0);
    if (bad2) atomicAnd(&ok2, 0);
    __syncthreads();
    if (threadIdx.x == 0) g_mask_mode = ok4 ? 2 : (ok2 ? 1 : 0);
}

__global__ void convert_mask_kernel(const void* __restrict__ M)
{
    int i = blockIdx.x * blockDim.x + threadIdx.x;
    if (i >= Bb * Ss) return;
    int mode = g_mask_mode;
    unsigned char masked;
    if (mode == 2)      masked = (((const unsigned int*)M)[i]   != 0u);
    else if (mode == 1) masked = (((const unsigned short*)M)[i] != 0u);
    else                masked = (((const unsigned char*)M)[i]  != 0u);
    g_mask_bytes[i] = masked;
}

__global__ void __launch_bounds__(NT, 1)
attn_fwd_kernel(const float* __restrict__ Qg, const float* __restrict__ Kg,
                const float* __restrict__ Vg, float* __restrict__ Og)
{
    extern __shared__ float smem[];
    float* Qs = smem + OFF_Q;
    float* Ks = smem + OFF_K;
    float* Vs = smem + OFF_V;
    float* Ps = smem + OFF_P;

    const int b    = blockIdx.y;
    const int m0   = blockIdx.x * BM;
    const int tid  = threadIdx.x;
    const int tx   = tid & 15;
    const int ty   = tid >> 4;
    const int lane = tid & 31;
    const int warp = tid >> 5;

    const float* Qb = Qg + (size_t)b * Ss * Dd;
    const float* Kb = Kg + (size_t)b * Ss * Dd;
    const float* Vb = Vg + (size_t)b * Ss * Dd;
    const unsigned char* Mb = g_mask_bytes + (size_t)b * Ss;

    // ---- Q tile transposed into Qs[d][r] (conflict-free STS) ----
    #pragma unroll
    for (int it = 0; it < 16; ++it) {
        int chunk = it * 8 + warp;
        int d4 = chunk & 31;
        int rb = chunk >> 5;
        int r  = rb * 32 + lane;
        float4 q = *reinterpret_cast<const float4*>(Qb + (size_t)(m0 + r) * Dd + 4 * d4);
        Qs[(4 * d4 + 0) * BM + r] = q.x;
        Qs[(4 * d4 + 1) * BM + r] = q.y;
        Qs[(4 * d4 + 2) * BM + r] = q.z;
        Qs[(4 * d4 + 3) * BM + r] = q.w;
    }

    // packed O accumulators: o2[i][c2] = (O[row 8ty+i][8tx+2c2], ...[+1])
    unsigned long long o2[8][4];
    float mrow[8], lrow[8];
    #pragma unroll
    for (int i = 0; i < 8; ++i) {
        mrow[i] = -1e30f;
        lrow[i] = 0.0f;
        #pragma unroll
        for (int c = 0; c < 4; ++c) o2[i][c] = 0ULL;
    }

    const float inv_scale = 0.08838834764831845f; // 1/sqrt(128)

    for (int n0 = 0; n0 < Ss; n0 += BN) {
        __syncthreads();

        // ---- K tile transposed: Ks[d][r] ----
        #pragma unroll
        for (int it = 0; it < 8; ++it) {
            int chunk = it * 8 + warp;
            int d4 = chunk & 31;
            int rb = chunk >> 5;
            int r  = rb * 32 + lane;
            float4 k = *reinterpret_cast<const float4*>(Kb + (size_t)(n0 + r) * Dd + 4 * d4);
            Ks[(4 * d4 + 0) * BN + r] = k.x;
            Ks[(4 * d4 + 1) * BN + r] = k.y;
            Ks[(4 * d4 + 2) * BN + r] = k.z;
            Ks[(4 * d4 + 3) * BN + r] = k.w;
        }
        // ---- V tile: coalesced copy ----
        #pragma unroll
        for (int it = 0; it < 8; ++it) {
            int f  = it * NT + tid;
            int n  = f >> 5;
            int d4 = f & 31;
            float4 v = *reinterpret_cast<const float4*>(Vb + (size_t)(n0 + n) * Dd + 4 * d4);
            *reinterpret_cast<float4*>(Vs + n * Dd + 4 * d4) = v;
        }
        uchar4 mk = *reinterpret_cast<const uchar4*>(Mb + n0 + 4 * tx);

        __syncthreads();

        // ---- S = Q K^T, packed over query-row pairs ----
        // s2[i2][j] = (S[8ty+2*i2][4tx+j], S[8ty+2*i2+1][4tx+j])
        unsigned long long s2[4][4];
        #pragma unroll
        for (int i2 = 0; i2 < 4; ++i2)
            #pragma unroll
            for (int j = 0; j < 4; ++j) s2[i2][j] = 0ULL;

        #pragma unroll 4
        for (int d = 0; d < Dd; ++d) {
            // adjacent rows contiguous in Qs[d][*] -> packed pairs free
            ulonglong2 qa = *reinterpret_cast<const ulonglong2*>(Qs + d * BM + 8 * ty);
            ulonglong2 qb = *reinterpret_cast<const ulonglong2*>(Qs + d * BM + 8 * ty + 4);
            unsigned long long qp[4] = {qa.x, qa.y, qb.x, qb.y};
            float4 kf = *reinterpret_cast<const float4*>(Ks + d * BN + 4 * tx);
            unsigned long long kd[4] = {dup2(kf.x), dup2(kf.y), dup2(kf.z), dup2(kf.w)};
            #pragma unroll
            for (int i2 = 0; i2 < 4; ++i2)
                #pragma unroll
                for (int j = 0; j < 4; ++j)
                    fma2(s2[i2][j], qp[i2], kd[j]);
        }

        // unpack scores
        float s[8][4];
        #pragma unroll
        for (int i2 = 0; i2 < 4; ++i2)
            #pragma unroll
            for (int j = 0; j < 4; ++j) {
                float2 f = unpk(s2[i2][j]);
                s[2 * i2 + 0][j] = f.x;
                s[2 * i2 + 1][j] = f.y;
            }

        // ---- scale + mask + online softmax ----
        const bool mj[4] = {mk.x != 0, mk.y != 0, mk.z != 0, mk.w != 0};
        #pragma unroll
        for (int i = 0; i < 8; ++i) {
            float tm = -1e30f;
            #pragma unroll
            for (int j = 0; j < 4; ++j) {
                float v = s[i][j] * inv_scale;
                if (mj[j]) v = -1e30f;
                s[i][j] = v;
                tm = fmaxf(tm, v);
            }
            tm = fmaxf(tm, __shfl_xor_sync(0xffffffffu, tm, 1));
            tm = fmaxf(tm, __shfl_xor_sync(0xffffffffu, tm, 2));
            tm = fmaxf(tm, __shfl_xor_sync(0xffffffffu, tm, 4));
            tm = fmaxf(tm, __shfl_xor_sync(0xffffffffu, tm, 8));

            float mnew  = fmaxf(mrow[i], tm);
            float alpha = __expf(mrow[i] - mnew);
            mrow[i] = mnew;

            float ps = 0.0f;
            #pragma unroll
            for (int j = 0; j < 4; ++j) {
                float p = __expf(s[i][j] - mnew);
                s[i][j] = p;
                ps += p;
            }
            ps += __shfl_xor_sync(0xffffffffu, ps, 1);
            ps += __shfl_xor_sync(0xffffffffu, ps, 2);
            ps += __shfl_xor_sync(0xffffffffu, ps, 4);
            ps += __shfl_xor_sync(0xffffffffu, ps, 8);

            lrow[i] = lrow[i] * alpha + ps;
            unsigned long long ad = dup2(alpha);
            #pragma unroll
            for (int c = 0; c < 4; ++c) mul2(o2[i][c], ad);
        }

        // ---- store P tile ----
        #pragma unroll
        for (int i = 0; i < 8; ++i) {
            float4 pv = make_float4(s[i][0], s[i][1], s[i][2], s[i][3]);
            *reinterpret_cast<float4*>(Ps + (8 * ty + i) * PP + 4 * tx) = pv;
        }
        __syncthreads();

        // ---- O += P @ V, packed over output-column pairs ----
        #pragma unroll 2
        for (int j = 0; j < BN; ++j) {
            ulonglong2 va = *reinterpret_cast<const ulonglong2*>(Vs + j * Dd + 8 * tx);
            ulonglong2 vb = *reinterpret_cast<const ulonglong2*>(Vs + j * Dd + 8 * tx + 4);
            unsigned long long vp[4] = {va.x, va.y, vb.x, vb.y};
            unsigned long long pd[8];
            #pragma unroll
            for (int i = 0; i < 8; ++i) pd[i] = dup2(Ps[(8 * ty + i) * PP + j]);
            #pragma unroll
            for (int i = 0; i < 8; ++i)
                #pragma unroll
                for (int c = 0; c < 4; ++c)
                    fma2(o2[i][c], pd[i], vp[c]);
        }
    }

    // ---- epilogue: packed normalize, 32B vector stores ----
    #pragma unroll
    for (int i = 0; i < 8; ++i) {
        unsigned long long il = dup2(1.0f / lrow[i]);
        #pragma unroll
        for (int c = 0; c < 4; ++c) mul2(o2[i][c], il);
        size_t row = (size_t)b * Ss + (m0 + 8 * ty + i);
        ulonglong2 w0; w0.x = o2[i][0]; w0.y = o2[i][1];
        ulonglong2 w1; w1.x = o2[i][2]; w1.y = o2[i][3];
        *reinterpret_cast<ulonglong2*>(Og + row * Dd + 8 * tx)     = w0;
        *reinterpret_cast<ulonglong2*>(Og + row * Dd + 8 * tx + 4) = w1;
    }
}

extern "C" void kernel_launch(void* const* d_in, const int* in_sizes, int n_in,
                              void* d_out, int out_size)
{
    const float* q = (const float*)d_in[0];
    const float* k = (const float*)d_in[1];
    const float* v = (const float*)d_in[2];
    const void*  m = d_in[3];
    float* out = (float*)d_out;

    detect_mask_mode_kernel<<<1, 256>>>((const unsigned int*)m);
    convert_mask_kernel<<<(Bb * Ss + 255) / 256, 256>>>(m);

    size_t smem_bytes = (size_t)SMEM_FLOATS * sizeof(float);
    cudaFuncSetAttribute(attn_fwd_kernel,
                         cudaFuncAttributeMaxDynamicSharedMemorySize,
                         (int)smem_bytes);
    dim3 grid(Ss / BM, Bb);
    attn_fwd_kernel<<<grid, NT, smem_bytes>>>(q, k, v, out);
}

// round 5
// speedup vs baseline: 1.0722x; 1.0044x over previous
#include <cuda_runtime.h>

namespace {
constexpr int Bb = 8;
constexpr int Ss = 2048;
constexpr int Dd = 128;
constexpr int BM = 128;   // query rows per CTA
constexpr int BN = 128;   // keys per tile
constexpr int NT = 256;   // threads per CTA (16x16)
constexpr int PP = 132;   // Ps row pitch (floats), + per-row monotone skew

constexpr int OFF_Q = 0;                 // Qs[D][BM]      16384 floats
constexpr int OFF_K = OFF_Q + Dd * BM;   // Ks[D][BN] / Ps union
constexpr int KP_UNION = 17440;          // >= max(16384, Ps extent 16952)
constexpr int OFF_V = OFF_K + KP_UNION;  // Vs[BN][D]      16384 floats
constexpr int SMEM_FLOATS = OFF_V + BN * Dd;
}

// ---- packed f32x2 helpers (Blackwell FFMA2 path) ----
__device__ __forceinline__ void fma2(unsigned long long& d,
                                     unsigned long long a,
                                     unsigned long long b) {
    asm("fma.rn.f32x2 %0, %1, %2, %0;" : "+l"(d) : "l"(a), "l"(b));
}
__device__ __forceinline__ void mul2(unsigned long long& d,
                                     unsigned long long a) {
    asm("mul.rn.f32x2 %0, %0, %1;" : "+l"(d) : "l"(a));
}
__device__ __forceinline__ unsigned long long dup2(float x) {
    unsigned long long r;
    asm("mov.b64 %0, {%1, %1};" : "=l"(r) : "f"(x));
    return r;
}
__device__ __forceinline__ float2 unpk(unsigned long long v) {
    float2 f;
    asm("mov.b64 {%0, %1}, %2;" : "=f"(f.x), "=f"(f.y) : "l"(v));
    return f;
}

// Normalized mask scratch + detected element width.
__device__ unsigned char g_mask_bytes[Bb * Ss];
__device__ int g_mask_mode; // 0 = 1-byte, 1 = bf16, 2 = 4-byte (int32/fp32)

__global__ void detect_mask_mode_kernel(const unsigned int* __restrict__ M)
{
    __shared__ int ok4, ok2;
    if (threadIdx.x == 0) { ok4 = 1; ok2 = 1; }
    __syncthreads();
    int bad4 = 0, bad2 = 0;
    for (int i = threadIdx.x; i < 2048; i += blockDim.x) {
        unsigned int w = M[i];
        if (!(w == 0u || w == 1u || w == 0x3F800000u)) bad4 = 1;
        unsigned int lo = w & 0xFFFFu, hi = w >> 16;
        if (!((lo == 0u || lo == 0x3F80u) && (hi == 0u || hi == 0x3F80u))) bad2 = 1;
    }
    if (bad4) atomicAnd(&ok4, 0);
    if (bad2) atomicAnd(&ok2, 0);
    __syncthreads();
    if (threadIdx.x == 0) g_mask_mode = ok4 ? 2 : (ok2 ? 1 : 0);
}

__global__ void convert_mask_kernel(const void* __restrict__ M)
{
    int i = blockIdx.x * blockDim.x + threadIdx.x;
    if (i >= Bb * Ss) return;
    int mode = g_mask_mode;
    unsigned char masked;
    if (mode == 2)      masked = (((const unsigned int*)M)[i]   != 0u);
    else if (mode == 1) masked = (((const unsigned short*)M)[i] != 0u);
    else                masked = (((const unsigned char*)M)[i]  != 0u);
    g_mask_bytes[i] = masked;
}

__global__ void __launch_bounds__(NT, 1)
attn_fwd_kernel(const float* __restrict__ Qg, const float* __restrict__ Kg,
                const float* __restrict__ Vg, float* __restrict__ Og)
{
    extern __shared__ float smem[];
    float* Qs = smem + OFF_Q;
    float* Ks = smem + OFF_K;
    float* Vs = smem + OFF_V;
    float* Ps = smem + OFF_K;   // aliases Ks (K dead once S is in registers)

    const int b    = blockIdx.y;
    const int m0   = blockIdx.x * BM;
    const int tid  = threadIdx.x;
    const int tx   = tid & 15;   // 8 keys / 8 out-cols each
    const int ty   = tid >> 4;   // 8 query rows each
    const int lane = tid & 31;
    const int warp = tid >> 5;
    // MONOTONE skew (fix vs R4): row extents never overlap since
    // skew(r) is non-decreasing in r and PP - 128 = 4 >= skew step.
    const int skew = ty * 4;

    const float* Qb = Qg + (size_t)b * Ss * Dd;
    const float* Kb = Kg + (size_t)b * Ss * Dd;
    const float* Vb = Vg + (size_t)b * Ss * Dd;
    const unsigned char* Mb = g_mask_bytes + (size_t)b * Ss;

    // ---- Q tile transposed into Qs[d][r] (conflict-free STS) ----
    #pragma unroll
    for (int it = 0; it < 16; ++it) {
        int chunk = it * 8 + warp;   // 0..127 -> (rb 0..3, d4 0..31)
        int d4 = chunk & 31;
        int rb = chunk >> 5;
        int r  = rb * 32 + lane;
        float4 q = *reinterpret_cast<const float4*>(Qb + (size_t)(m0 + r) * Dd + 4 * d4);
        Qs[(4 * d4 + 0) * BM + r] = q.x;
        Qs[(4 * d4 + 1) * BM + r] = q.y;
        Qs[(4 * d4 + 2) * BM + r] = q.z;
        Qs[(4 * d4 + 3) * BM + r] = q.w;
    }

    // packed O accumulators: o2[i][c2] = (O[8ty+i][8tx+2c2], [+1])
    unsigned long long o2[8][4];
    float mrow[8], lrow[8];
    #pragma unroll
    for (int i = 0; i < 8; ++i) {
        mrow[i] = -1e30f;
        lrow[i] = 0.0f;
        #pragma unroll
        for (int c = 0; c < 4; ++c) o2[i][c] = 0ULL;
    }

    const float inv_scale = 0.08838834764831845f; // 1/sqrt(128)

    for (int n0 = 0; n0 < Ss; n0 += BN) {
        __syncthreads();   // (A) prev PV done reading Ps/Vs

        // ---- K tile transposed: Ks[d][r], r = key 0..127 ----
        #pragma unroll
        for (int it = 0; it < 16; ++it) {
            int chunk = it * 8 + warp;
            int d4 = chunk & 31;
            int rb = chunk >> 5;
            int r  = rb * 32 + lane;
            float4 k = *reinterpret_cast<const float4*>(Kb + (size_t)(n0 + r) * Dd + 4 * d4);
            Ks[(4 * d4 + 0) * BN + r] = k.x;
            Ks[(4 * d4 + 1) * BN + r] = k.y;
            Ks[(4 * d4 + 2) * BN + r] = k.z;
            Ks[(4 * d4 + 3) * BN + r] = k.w;
        }
        // ---- V tile: coalesced copy ----
        #pragma unroll
        for (int it = 0; it < 16; ++it) {
            int f  = it * NT + tid;      // 0..4095 float4s
            int n  = f >> 5;
            int d4 = f & 31;
            float4 v = *reinterpret_cast<const float4*>(Vb + (size_t)(n0 + n) * Dd + 4 * d4);
            *reinterpret_cast<float4*>(Vs + n * Dd + 4 * d4) = v;
        }
        // mask bytes for this thread's 8 keys
        uint2 mw = *reinterpret_cast<const uint2*>(Mb + n0 + 8 * tx);

        __syncthreads();   // (B) K/V tiles visible

        // ---- S = Q K^T : 8 rows x 8 keys per thread, packed row-pairs ----
        unsigned long long s2[4][8];
        #pragma unroll
        for (int i2 = 0; i2 < 4; ++i2)
            #pragma unroll
            for (int j = 0; j < 8; ++j) s2[i2][j] = 0ULL;

        #pragma unroll 2
        for (int d = 0; d < Dd; ++d) {
            ulonglong2 qa = *reinterpret_cast<const ulonglong2*>(Qs + d * BM + 8 * ty);
            ulonglong2 qb = *reinterpret_cast<const ulonglong2*>(Qs + d * BM + 8 * ty + 4);
            unsigned long long qp[4] = {qa.x, qa.y, qb.x, qb.y};
            float4 k0 = *reinterpret_cast<const float4*>(Ks + d * BN + 8 * tx);
            float4 k1 = *reinterpret_cast<const float4*>(Ks + d * BN + 8 * tx + 4);
            unsigned long long kd[8] = {dup2(k0.x), dup2(k0.y), dup2(k0.z), dup2(k0.w),
                                        dup2(k1.x), dup2(k1.y), dup2(k1.z), dup2(k1.w)};
            #pragma unroll
            for (int i2 = 0; i2 < 4; ++i2)
                #pragma unroll
                for (int j = 0; j < 8; ++j)
                    fma2(s2[i2][j], qp[i2], kd[j]);
        }

        // unpack scores
        float s[8][8];
        #pragma unroll
        for (int i2 = 0; i2 < 4; ++i2)
            #pragma unroll
            for (int j = 0; j < 8; ++j) {
                float2 f = unpk(s2[i2][j]);
                s[2 * i2 + 0][j] = f.x;
                s[2 * i2 + 1][j] = f.y;
            }

        // ---- scale + mask + online softmax (registers + shuffles only) ----
        bool mj[8];
        #pragma unroll
        for (int t = 0; t < 4; ++t) {
            mj[t]     = ((mw.x >> (8 * t)) & 0xFFu) != 0u;
            mj[t + 4] = ((mw.y >> (8 * t)) & 0xFFu) != 0u;
        }
        #pragma unroll
        for (int i = 0; i < 8; ++i) {
            float tm = -1e30f;
            #pragma unroll
            for (int j = 0; j < 8; ++j) {
                float v = s[i][j] * inv_scale;
                if (mj[j]) v = -1e30f;
                s[i][j] = v;
                tm = fmaxf(tm, v);
            }
            tm = fmaxf(tm, __shfl_xor_sync(0xffffffffu, tm, 1));
            tm = fmaxf(tm, __shfl_xor_sync(0xffffffffu, tm, 2));
            tm = fmaxf(tm, __shfl_xor_sync(0xffffffffu, tm, 4));
            tm = fmaxf(tm, __shfl_xor_sync(0xffffffffu, tm, 8));

            float mnew  = fmaxf(mrow[i], tm);
            float alpha = __expf(mrow[i] - mnew);
            mrow[i] = mnew;

            float ps = 0.0f;
            #pragma unroll
            for (int j = 0; j < 8; ++j) {
                float p = __expf(s[i][j] - mnew);
                s[i][j] = p;
                ps += p;
            }
            ps += __shfl_xor_sync(0xffffffffu, ps, 1);
            ps += __shfl_xor_sync(0xffffffffu, ps, 2);
            ps += __shfl_xor_sync(0xffffffffu, ps, 4);
            ps += __shfl_xor_sync(0xffffffffu, ps, 8);

            lrow[i] = lrow[i] * alpha + ps;
            unsigned long long ad = dup2(alpha);
            #pragma unroll
            for (int c = 0; c < 4; ++c) mul2(o2[i][c], ad);
        }

        __syncthreads();   // (C) everyone done reading Ks before P overwrites it

        // ---- store P tile (monotone skewed rows) ----
        #pragma unroll
        for (int i = 0; i < 8; ++i) {
            float* prow = Ps + (8 * ty + i) * PP + skew + 8 * tx;
            *reinterpret_cast<float4*>(prow)     = make_float4(s[i][0], s[i][1], s[i][2], s[i][3]);
            *reinterpret_cast<float4*>(prow + 4) = make_float4(s[i][4], s[i][5], s[i][6], s[i][7]);
        }
        __syncthreads();   // (D) P visible

        // ---- O += P @ V, packed over output-column pairs ----
        #pragma unroll 2
        for (int j = 0; j < BN; ++j) {
            ulonglong2 va = *reinterpret_cast<const ulonglong2*>(Vs + j * Dd + 8 * tx);
            ulonglong2 vb = *reinterpret_cast<const ulonglong2*>(Vs + j * Dd + 8 * tx + 4);
            unsigned long long vp[4] = {va.x, va.y, vb.x, vb.y};
            unsigned long long pd[8];
            #pragma unroll
            for (int i = 0; i < 8; ++i)
                pd[i] = dup2(Ps[(8 * ty + i) * PP + skew + j]);
            #pragma unroll
            for (int i = 0; i < 8; ++i)
                #pragma unroll
                for (int c = 0; c < 4; ++c)
                    fma2(o2[i][c], pd[i], vp[c]);
        }
    }

    // ---- epilogue: packed normalize, 32B vector stores ----
    #pragma unroll
    for (int i = 0; i < 8; ++i) {
        unsigned long long il = dup2(1.0f / lrow[i]);
        #pragma unroll
        for (int c = 0; c < 4; ++c) mul2(o2[i][c], il);
        size_t row = (size_t)b * Ss + (m0 + 8 * ty + i);
        ulonglong2 w0; w0.x = o2[i][0]; w0.y = o2[i][1];
        ulonglong2 w1; w1.x = o2[i][2]; w1.y = o2[i][3];
        *reinterpret_cast<ulonglong2*>(Og + row * Dd + 8 * tx)     = w0;
        *reinterpret_cast<ulonglong2*>(Og + row * Dd + 8 * tx + 4) = w1;
    }
}

extern "C" void kernel_launch(void* const* d_in, const int* in_sizes, int n_in,
                              void* d_out, int out_size)
{
    const float* q = (const float*)d_in[0];
    const float* k = (const float*)d_in[1];
    const float* v = (const float*)d_in[2];
    const void*  m = d_in[3];
    float* out = (float*)d_out;

    detect_mask_mode_kernel<<<1, 256>>>((const unsigned int*)m);
    convert_mask_kernel<<<(Bb * Ss + 255) / 256, 256>>>(m);

    size_t smem_bytes = (size_t)SMEM_FLOATS * sizeof(float);
    cudaFuncSetAttribute(attn_fwd_kernel,
                         cudaFuncAttributeMaxDynamicSharedMemorySize,
                         (int)smem_bytes);
    dim3 grid(Ss / BM, Bb);
    attn_fwd_kernel<<<grid, NT, smem_bytes>>>(q, k, v, out);
}

// round 6
// speedup vs baseline: 2.9167x; 2.7202x over previous
#include <cuda_runtime.h>
#include <cuda_bf16.h>
#include <cstdint>

namespace {
constexpr int Bb = 8, Ss = 2048, Dd = 128;
constexpr int BM = 128;   // query rows per CTA
constexpr int BN = 64;    // keys per tile
constexpr int NT = 256;   // 8 warps
constexpr int N4 = Bb * Ss * Dd / 4;   // float4 count per tensor = 524288

// smem byte offsets (bf16 tiles, 256B rows, XOR-swizzled 16B granules)
constexpr int QH_OFF = 0;        // 128 rows * 256B = 32768
constexpr int QL_OFF = 32768;
constexpr int KH_OFF = 65536;    // 64 rows * 256B = 16384
constexpr int KL_OFF = 81920;
constexpr int VH_OFF = 98304;
constexpr int VL_OFF = 114688;
constexpr int MK_OFF = 131072;   // 64 mask bytes
constexpr int SMEM_BYTES = 131072 + 64;
}

// bf16 hi/lo split scratch (static device arrays: allocation-free)
__device__ uint2 gQh[N4], gQl[N4], gKh[N4], gKl[N4], gVh[N4], gVl[N4];
__device__ unsigned char g_mask_bytes[Bb * Ss];
__device__ int g_mask_mode;

// ---------------- prepass kernels ----------------
__global__ void detect_mask_mode_kernel(const unsigned int* __restrict__ M)
{
    __shared__ int ok4, ok2;
    if (threadIdx.x == 0) { ok4 = 1; ok2 = 1; }
    __syncthreads();
    int bad4 = 0, bad2 = 0;
    for (int i = threadIdx.x; i < 2048; i += blockDim.x) {
        unsigned int w = M[i];
        if (!(w == 0u || w == 1u || w == 0x3F800000u)) bad4 = 1;
        unsigned int lo = w & 0xFFFFu, hi = w >> 16;
        if (!((lo == 0u || lo == 0x3F80u) && (hi == 0u || hi == 0x3F80u))) bad2 = 1;
    }
    if (bad4) atomicAnd(&ok4, 0);
    if (bad2) atomicAnd(&ok2, 0);
    __syncthreads();
    if (threadIdx.x == 0) g_mask_mode = ok4 ? 2 : (ok2 ? 1 : 0);
}

__global__ void convert_mask_kernel(const void* __restrict__ M)
{
    int i = blockIdx.x * blockDim.x + threadIdx.x;
    if (i >= Bb * Ss) return;
    int mode = g_mask_mode;
    unsigned char masked;
    if (mode == 2)      masked = (((const unsigned int*)M)[i]   != 0u);
    else if (mode == 1) masked = (((const unsigned short*)M)[i] != 0u);
    else                masked = (((const unsigned char*)M)[i]  != 0u);
    g_mask_bytes[i] = masked;
}

__device__ __forceinline__ void split4(float4 f, uint2& hi, uint2& lo)
{
    __nv_bfloat162 h0 = __float22bfloat162_rn(make_float2(f.x, f.y));
    __nv_bfloat162 h1 = __float22bfloat162_rn(make_float2(f.z, f.w));
    float2 d0 = __bfloat1622float2(h0);
    float2 d1 = __bfloat1622float2(h1);
    __nv_bfloat162 l0 = __float22bfloat162_rn(make_float2(f.x - d0.x, f.y - d0.y));
    __nv_bfloat162 l1 = __float22bfloat162_rn(make_float2(f.z - d1.x, f.w - d1.y));
    hi.x = reinterpret_cast<uint32_t&>(h0); hi.y = reinterpret_cast<uint32_t&>(h1);
    lo.x = reinterpret_cast<uint32_t&>(l0); lo.y = reinterpret_cast<uint32_t&>(l1);
}

__global__ void split_bf16_kernel(const float4* __restrict__ Q,
                                  const float4* __restrict__ K,
                                  const float4* __restrict__ V)
{
    int i = blockIdx.x * blockDim.x + threadIdx.x;
    if (i >= N4) return;
    uint2 h, l;
    split4(Q[i], h, l); gQh[i] = h; gQl[i] = l;
    split4(K[i], h, l); gKh[i] = h; gKl[i] = l;
    split4(V[i], h, l); gVh[i] = h; gVl[i] = l;
}

// ---------------- mma / ldmatrix helpers ----------------
__device__ __forceinline__ void ldsm4(uint32_t* r, uint32_t addr)
{
    asm volatile("ldmatrix.sync.aligned.m8n8.x4.shared.b16 {%0,%1,%2,%3},[%4];"
        : "=r"(r[0]), "=r"(r[1]), "=r"(r[2]), "=r"(r[3]) : "r"(addr));
}
__device__ __forceinline__ void ldsm4t(uint32_t* r, uint32_t addr)
{
    asm volatile("ldmatrix.sync.aligned.m8n8.x4.trans.shared.b16 {%0,%1,%2,%3},[%4];"
        : "=r"(r[0]), "=r"(r[1]), "=r"(r[2]), "=r"(r[3]) : "r"(addr));
}
__device__ __forceinline__ void mma16816(float* c, const uint32_t* a,
                                         uint32_t b0, uint32_t b1)
{
    asm volatile("mma.sync.aligned.m16n8k16.row.col.f32.bf16.bf16.f32 "
        "{%0,%1,%2,%3},{%4,%5,%6,%7},{%8,%9},{%0,%1,%2,%3};"
        : "+f"(c[0]), "+f"(c[1]), "+f"(c[2]), "+f"(c[3])
        : "r"(a[0]), "r"(a[1]), "r"(a[2]), "r"(a[3]), "r"(b0), "r"(b1));
}

// ---------------- main attention kernel ----------------
__global__ void __launch_bounds__(NT, 1)
attn_fwd_kernel(float* __restrict__ Og)
{
    extern __shared__ char smem[];
    uint32_t sb;
    asm("{.reg .u64 t; cvta.to.shared.u64 t, %1; cvt.u32.u64 %0, t;}"
        : "=r"(sb) : "l"(smem));

    const int b    = blockIdx.y;
    const int m0   = blockIdx.x * BM;
    const int tid  = threadIdx.x;
    const int lane = tid & 31;
    const int warp = tid >> 5;
    const int b2048 = b * Ss;

    const uint4* Qh4 = reinterpret_cast<const uint4*>(gQh);
    const uint4* Ql4 = reinterpret_cast<const uint4*>(gQl);
    const uint4* Kh4 = reinterpret_cast<const uint4*>(gKh);
    const uint4* Kl4 = reinterpret_cast<const uint4*>(gKl);
    const uint4* Vh4 = reinterpret_cast<const uint4*>(gVh);
    const uint4* Vl4 = reinterpret_cast<const uint4*>(gVl);

    // ---- stage Q tile (hi+lo), swizzled ----
    #pragma unroll
    for (int i = 0; i < 8; ++i) {
        int gi = i * NT + tid;           // 0..2047
        int row = gi >> 4, g = gi & 15;
        int sw = row * 16 + (g ^ (row & 7));
        size_t qidx = (size_t)(b2048 + m0 + row) * 16 + g;
        reinterpret_cast<uint4*>(smem + QH_OFF)[sw] = Qh4[qidx];
        reinterpret_cast<uint4*>(smem + QL_OFF)[sw] = Ql4[qidx];
    }

    // per-thread ldmatrix address patterns
    const int arow = 16 * warp + (lane & 15);     // A-frag row (Q)
    const int ag   = lane >> 4;                   // granule 0/1
    const int brow = (lane & 7) + ((lane & 16) >> 1);  // B-frag (K) row in ntp block
    const int bg   = (lane >> 3) & 1;
    const int vrl  = lane & 15;                   // V-frag row within key chunk
    const int ct2  = (lane & 3) * 2;              // col-pair offset
    const int gr   = lane >> 2;                   // row group

    float o[16][4];
    #pragma unroll
    for (int nt = 0; nt < 16; ++nt)
        #pragma unroll
        for (int c = 0; c < 4; ++c) o[nt][c] = 0.0f;
    float mst0 = -1e30f, mst1 = -1e30f, lsum0 = 0.0f, lsum1 = 0.0f;
    const float inv_scale = 0.08838834764831845f;

    for (int n0 = 0; n0 < Ss; n0 += BN) {
        __syncthreads();   // previous tile's reads done

        // ---- stage K,V (hi+lo) + mask ----
        #pragma unroll
        for (int i = 0; i < 4; ++i) {
            int gi = i * NT + tid;       // 0..1023
            int row = gi >> 4, g = gi & 15;
            int sw = row * 16 + (g ^ (row & 7));
            size_t gidx = (size_t)(b2048 + n0 + row) * 16 + g;
            reinterpret_cast<uint4*>(smem + KH_OFF)[sw] = Kh4[gidx];
            reinterpret_cast<uint4*>(smem + KL_OFF)[sw] = Kl4[gidx];
            reinterpret_cast<uint4*>(smem + VH_OFF)[sw] = Vh4[gidx];
            reinterpret_cast<uint4*>(smem + VL_OFF)[sw] = Vl4[gidx];
        }
        if (tid < 16)
            reinterpret_cast<uint32_t*>(smem + MK_OFF)[tid] =
                reinterpret_cast<const uint32_t*>(g_mask_bytes + b2048 + n0)[tid];
        __syncthreads();

        // ---- S = Q K^T (3-term bf16 split) ----
        float s[8][4];
        #pragma unroll
        for (int nt = 0; nt < 8; ++nt)
            #pragma unroll
            for (int c = 0; c < 4; ++c) s[nt][c] = 0.0f;

        #pragma unroll
        for (int kc = 0; kc < 8; ++kc) {
            uint32_t qh[4], ql[4];
            uint32_t qoff = (uint32_t)(arow * 256 + (((2 * kc + ag) ^ (arow & 7)) << 4));
            ldsm4(qh, sb + QH_OFF + qoff);
            ldsm4(ql, sb + QL_OFF + qoff);
            #pragma unroll
            for (int ntp = 0; ntp < 4; ++ntp) {
                uint32_t kh[4], kl[4];
                uint32_t koff = (uint32_t)((16 * ntp + brow) * 256 +
                                           (((2 * kc + bg) ^ (brow & 7)) << 4));
                ldsm4(kh, sb + KH_OFF + koff);
                ldsm4(kl, sb + KL_OFF + koff);
                mma16816(s[2 * ntp],     qh, kh[0], kh[1]);
                mma16816(s[2 * ntp],     qh, kl[0], kl[1]);
                mma16816(s[2 * ntp],     ql, kh[0], kh[1]);
                mma16816(s[2 * ntp + 1], qh, kh[2], kh[3]);
                mma16816(s[2 * ntp + 1], qh, kl[2], kl[3]);
                mma16816(s[2 * ntp + 1], ql, kh[2], kh[3]);
            }
        }

        // ---- scale + mask + online softmax (warp-local rows) ----
        float tm0 = -1e30f, tm1 = -1e30f;
        #pragma unroll
        for (int nt = 0; nt < 8; ++nt) {
            uchar2 mk = *reinterpret_cast<const uchar2*>(smem + MK_OFF + 8 * nt + ct2);
            float v0 = s[nt][0] * inv_scale; if (mk.x) v0 = -1e30f;
            float v1 = s[nt][1] * inv_scale; if (mk.y) v1 = -1e30f;
            float v2 = s[nt][2] * inv_scale; if (mk.x) v2 = -1e30f;
            float v3 = s[nt][3] * inv_scale; if (mk.y) v3 = -1e30f;
            s[nt][0] = v0; s[nt][1] = v1; s[nt][2] = v2; s[nt][3] = v3;
            tm0 = fmaxf(tm0, fmaxf(v0, v1));
            tm1 = fmaxf(tm1, fmaxf(v2, v3));
        }
        tm0 = fmaxf(tm0, __shfl_xor_sync(0xffffffffu, tm0, 1));
        tm0 = fmaxf(tm0, __shfl_xor_sync(0xffffffffu, tm0, 2));
        tm1 = fmaxf(tm1, __shfl_xor_sync(0xffffffffu, tm1, 1));
        tm1 = fmaxf(tm1, __shfl_xor_sync(0xffffffffu, tm1, 2));

        float mn0 = fmaxf(mst0, tm0), mn1 = fmaxf(mst1, tm1);
        float al0 = __expf(mst0 - mn0), al1 = __expf(mst1 - mn1);
        mst0 = mn0; mst1 = mn1;

        uint32_t ph[8][2], pl[8][2];
        float ps0 = 0.0f, ps1 = 0.0f;
        #pragma unroll
        for (int nt = 0; nt < 8; ++nt) {
            float p0 = __expf(s[nt][0] - mn0);
            float p1 = __expf(s[nt][1] - mn0);
            float p2 = __expf(s[nt][2] - mn1);
            float p3 = __expf(s[nt][3] - mn1);
            ps0 += p0 + p1; ps1 += p2 + p3;
            __nv_bfloat162 h0 = __float22bfloat162_rn(make_float2(p0, p1));
            __nv_bfloat162 h1 = __float22bfloat162_rn(make_float2(p2, p3));
            float2 d0 = __bfloat1622float2(h0);
            float2 d1 = __bfloat1622float2(h1);
            __nv_bfloat162 l0 = __float22bfloat162_rn(make_float2(p0 - d0.x, p1 - d0.y));
            __nv_bfloat162 l1 = __float22bfloat162_rn(make_float2(p2 - d1.x, p3 - d1.y));
            ph[nt][0] = reinterpret_cast<uint32_t&>(h0);
            ph[nt][1] = reinterpret_cast<uint32_t&>(h1);
            pl[nt][0] = reinterpret_cast<uint32_t&>(l0);
            pl[nt][1] = reinterpret_cast<uint32_t&>(l1);
        }
        ps0 += __shfl_xor_sync(0xffffffffu, ps0, 1);
        ps0 += __shfl_xor_sync(0xffffffffu, ps0, 2);
        ps1 += __shfl_xor_sync(0xffffffffu, ps1, 1);
        ps1 += __shfl_xor_sync(0xffffffffu, ps1, 2);
        lsum0 = lsum0 * al0 + ps0;
        lsum1 = lsum1 * al1 + ps1;

        #pragma unroll
        for (int nt = 0; nt < 16; ++nt) {
            o[nt][0] *= al0; o[nt][1] *= al0;
            o[nt][2] *= al1; o[nt][3] *= al1;
        }

        // ---- O += P V (3-term split; P frags straight from registers) ----
        #pragma unroll
        for (int kc = 0; kc < 4; ++kc) {
            uint32_t ah[4] = {ph[2 * kc][0], ph[2 * kc][1],
                              ph[2 * kc + 1][0], ph[2 * kc + 1][1]};
            uint32_t al[4] = {pl[2 * kc][0], pl[2 * kc][1],
                              pl[2 * kc + 1][0], pl[2 * kc + 1][1]};
            #pragma unroll
            for (int ntp = 0; ntp < 8; ++ntp) {
                uint32_t vh[4], vl[4];
                uint32_t voff = (uint32_t)((16 * kc + vrl) * 256 +
                                           (((2 * ntp + ag) ^ (vrl & 7)) << 4));
                ldsm4t(vh, sb + VH_OFF + voff);
                ldsm4t(vl, sb + VL_OFF + voff);
                mma16816(o[2 * ntp],     ah, vh[0], vh[1]);
                mma16816(o[2 * ntp],     ah, vl[0], vl[1]);
                mma16816(o[2 * ntp],     al, vh[0], vh[1]);
                mma16816(o[2 * ntp + 1], ah, vh[2], vh[3]);
                mma16816(o[2 * ntp + 1], ah, vl[2], vl[3]);
                mma16816(o[2 * ntp + 1], al, vh[2], vh[3]);
            }
        }
    }

    // ---- epilogue ----
    float il0 = 1.0f / lsum0, il1 = 1.0f / lsum1;
    int r0 = m0 + 16 * warp + gr;
    float* O0 = Og + ((size_t)b2048 + r0) * Dd + ct2;
    float* O1 = O0 + 8 * Dd;
    #pragma unroll
    for (int nt = 0; nt < 16; ++nt) {
        *reinterpret_cast<float2*>(O0 + 8 * nt) =
            make_float2(o[nt][0] * il0, o[nt][1] * il0);
        *reinterpret_cast<float2*>(O1 + 8 * nt) =
            make_float2(o[nt][2] * il1, o[nt][3] * il1);
    }
}

extern "C" void kernel_launch(void* const* d_in, const int* in_sizes, int n_in,
                              void* d_out, int out_size)
{
    const float* q = (const float*)d_in[0];
    const float* k = (const float*)d_in[1];
    const float* v = (const float*)d_in[2];
    const void*  m = d_in[3];
    float* out = (float*)d_out;

    detect_mask_mode_kernel<<<1, 256>>>((const unsigned int*)m);
    convert_mask_kernel<<<(Bb * Ss + 255) / 256, 256>>>(m);
    split_bf16_kernel<<<(N4 + 255) / 256, 256>>>(
        (const float4*)q, (const float4*)k, (const float4*)v);

    cudaFuncSetAttribute(attn_fwd_kernel,
                         cudaFuncAttributeMaxDynamicSharedMemorySize, SMEM_BYTES);
    dim3 grid(Ss / BM, Bb);
    attn_fwd_kernel<<<grid, NT, SMEM_BYTES>>>(out);
}

// round 8
// speedup vs baseline: 3.1617x; 1.0840x over previous
#include <cuda_runtime.h>
#include <cuda_bf16.h>
#include <cstdint>

namespace {
constexpr int Bb = 8, Ss = 2048, Dd = 128;
constexpr int BM = 64;    // query rows per CTA
constexpr int BN = 64;    // keys per tile
constexpr int NT = 128;   // 4 warps
constexpr int N4 = Bb * Ss * Dd / 4;   // float4 count per tensor

// smem byte offsets (bf16 tiles, 256B rows, XOR-swizzled 16B granules)
constexpr int QH_OFF = 0;        // 64 rows * 256B = 16384
constexpr int QL_OFF = 16384;
constexpr int KH_OFF = 32768;
constexpr int KL_OFF = 49152;
constexpr int VH_OFF = 65536;
constexpr int VL_OFF = 81920;
constexpr int MK_OFF = 98304;    // 64 mask bytes
constexpr int SMEM_BYTES = 98304 + 64;
}

// bf16 hi/lo split scratch (static device arrays: allocation-free)
__device__ uint2 gQh[N4], gQl[N4], gKh[N4], gKl[N4], gVh[N4], gVl[N4];
__device__ unsigned char g_mask_bytes[Bb * Ss];
__device__ int g_mask_mode;

// ---------------- prepass kernels ----------------
__global__ void detect_mask_mode_kernel(const unsigned int* __restrict__ M)
{
    __shared__ int ok4, ok2;
    if (threadIdx.x == 0) { ok4 = 1; ok2 = 1; }
    __syncthreads();
    int bad4 = 0, bad2 = 0;
    for (int i = threadIdx.x; i < 2048; i += blockDim.x) {
        unsigned int w = M[i];
        if (!(w == 0u || w == 1u || w == 0x3F800000u)) bad4 = 1;
        unsigned int lo = w & 0xFFFFu, hi = w >> 16;
        if (!((lo == 0u || lo == 0x3F80u) && (hi == 0u || hi == 0x3F80u))) bad2 = 1;
    }
    if (bad4) atomicAnd(&ok4, 0);
    if (bad2) atomicAnd(&ok2, 0);
    __syncthreads();
    if (threadIdx.x == 0) g_mask_mode = ok4 ? 2 : (ok2 ? 1 : 0);
}

__global__ void convert_mask_kernel(const void* __restrict__ M)
{
    int i = blockIdx.x * blockDim.x + threadIdx.x;
    if (i >= Bb * Ss) return;
    int mode = g_mask_mode;
    unsigned char masked;
    if (mode == 2)      masked = (((const unsigned int*)M)[i]   != 0u);
    else if (mode == 1) masked = (((const unsigned short*)M)[i] != 0u);
    else                masked = (((const unsigned char*)M)[i]  != 0u);
    g_mask_bytes[i] = masked;
}

__device__ __forceinline__ void split4(float4 f, uint2& hi, uint2& lo)
{
    __nv_bfloat162 h0 = __float22bfloat162_rn(make_float2(f.x, f.y));
    __nv_bfloat162 h1 = __float22bfloat162_rn(make_float2(f.z, f.w));
    float2 d0 = __bfloat1622float2(h0);
    float2 d1 = __bfloat1622float2(h1);
    __nv_bfloat162 l0 = __float22bfloat162_rn(make_float2(f.x - d0.x, f.y - d0.y));
    __nv_bfloat162 l1 = __float22bfloat162_rn(make_float2(f.z - d1.x, f.w - d1.y));
    hi.x = reinterpret_cast<uint32_t&>(h0); hi.y = reinterpret_cast<uint32_t&>(h1);
    lo.x = reinterpret_cast<uint32_t&>(l0); lo.y = reinterpret_cast<uint32_t&>(l1);
}

__global__ void split_bf16_kernel(const float4* __restrict__ Q,
                                  const float4* __restrict__ K,
                                  const float4* __restrict__ V)
{
    int i = blockIdx.x * blockDim.x + threadIdx.x;
    if (i >= N4) return;
    uint2 h, l;
    split4(Q[i], h, l); gQh[i] = h; gQl[i] = l;
    split4(K[i], h, l); gKh[i] = h; gKl[i] = l;
    split4(V[i], h, l); gVh[i] = h; gVl[i] = l;
}

// ---------------- mma / ldmatrix / cp.async helpers ----------------
__device__ __forceinline__ void ldsm4(uint32_t* r, uint32_t addr)
{
    asm volatile("ldmatrix.sync.aligned.m8n8.x4.shared.b16 {%0,%1,%2,%3},[%4];"
        : "=r"(r[0]), "=r"(r[1]), "=r"(r[2]), "=r"(r[3]) : "r"(addr));
}
__device__ __forceinline__ void ldsm4t(uint32_t* r, uint32_t addr)
{
    asm volatile("ldmatrix.sync.aligned.m8n8.x4.trans.shared.b16 {%0,%1,%2,%3},[%4];"
        : "=r"(r[0]), "=r"(r[1]), "=r"(r[2]), "=r"(r[3]) : "r"(addr));
}
__device__ __forceinline__ void mma16816(float* c, const uint32_t* a,
                                         uint32_t b0, uint32_t b1)
{
    asm volatile("mma.sync.aligned.m16n8k16.row.col.f32.bf16.bf16.f32 "
        "{%0,%1,%2,%3},{%4,%5,%6,%7},{%8,%9},{%0,%1,%2,%3};"
        : "+f"(c[0]), "+f"(c[1]), "+f"(c[2]), "+f"(c[3])
        : "r"(a[0]), "r"(a[1]), "r"(a[2]), "r"(a[3]), "r"(b0), "r"(b1));
}
__device__ __forceinline__ void cpa16(uint32_t dst, const void* src)
{
    asm volatile("cp.async.cg.shared.global [%0], [%1], 16;"
                 :: "r"(dst), "l"(src) : "memory");
}
#define CPA_COMMIT() asm volatile("cp.async.commit_group;" ::: "memory")
#define CPA_WAIT0()  asm volatile("cp.async.wait_group 0;" ::: "memory")

// ---------------- main attention kernel ----------------
__global__ void __launch_bounds__(NT, 2)
attn_fwd_kernel(float* __restrict__ Og)
{
    extern __shared__ char smem[];
    uint32_t sb;
    asm("{.reg .u64 t; cvta.to.shared.u64 t, %1; cvt.u32.u64 %0, t;}"
        : "=r"(sb) : "l"(smem));

    const int b    = blockIdx.y;
    const int m0   = blockIdx.x * BM;
    const int tid  = threadIdx.x;
    const int lane = tid & 31;
    const int warp = tid >> 5;    // 0..3
    const int b2048 = b * Ss;

    const uint4* Qh4 = reinterpret_cast<const uint4*>(gQh);
    const uint4* Ql4 = reinterpret_cast<const uint4*>(gQl);
    const uint4* Kh4 = reinterpret_cast<const uint4*>(gKh);
    const uint4* Kl4 = reinterpret_cast<const uint4*>(gKl);
    const uint4* Vh4 = reinterpret_cast<const uint4*>(gVh);
    const uint4* Vl4 = reinterpret_cast<const uint4*>(gVl);

    // ---- stage Q tile (hi+lo) via cp.async, swizzled dst ----
    #pragma unroll
    for (int it = 0; it < 8; ++it) {
        int gi = it * NT + tid;          // 0..1023
        int row = gi >> 4, g = gi & 15;
        uint32_t sw16 = (uint32_t)(row * 16 + (g ^ (row & 7))) * 16u;
        size_t qidx = (size_t)(b2048 + m0 + row) * 16 + g;
        cpa16(sb + QH_OFF + sw16, Qh4 + qidx);
        cpa16(sb + QL_OFF + sw16, Ql4 + qidx);
    }
    CPA_COMMIT();

    // per-thread ldmatrix address patterns
    const int arow = 16 * warp + (lane & 15);          // A-frag row (Q)
    const int ag   = lane >> 4;                        // granule 0/1
    const int brow = (lane & 7) + ((lane & 16) >> 1);  // B-frag (K) row
    const int bg   = (lane >> 3) & 1;
    const int vrl  = lane & 15;                        // V-frag row
    const int ct2  = (lane & 3) * 2;                   // col-pair offset
    const int gr   = lane >> 2;                        // row group

    float o[16][4];
    #pragma unroll
    for (int nt = 0; nt < 16; ++nt)
        #pragma unroll
        for (int c = 0; c < 4; ++c) o[nt][c] = 0.0f;
    float mst0 = -1e30f, mst1 = -1e30f, lsum0 = 0.0f, lsum1 = 0.0f;
    const float inv_scale = 0.08838834764831845f;

    for (int n0 = 0; n0 < Ss; n0 += BN) {
        __syncthreads();   // previous tile's reads done

        // ---- stage K,V (hi+lo) via cp.async + mask ----
        #pragma unroll
        for (int it = 0; it < 8; ++it) {
            int gi = it * NT + tid;      // 0..1023
            int row = gi >> 4, g = gi & 15;
            uint32_t sw16 = (uint32_t)(row * 16 + (g ^ (row & 7))) * 16u;
            size_t gidx = (size_t)(b2048 + n0 + row) * 16 + g;
            cpa16(sb + KH_OFF + sw16, Kh4 + gidx);
            cpa16(sb + KL_OFF + sw16, Kl4 + gidx);
            cpa16(sb + VH_OFF + sw16, Vh4 + gidx);
            cpa16(sb + VL_OFF + sw16, Vl4 + gidx);
        }
        if (tid < 16)
            reinterpret_cast<uint32_t*>(smem + MK_OFF)[tid] =
                reinterpret_cast<const uint32_t*>(g_mask_bytes + b2048 + n0)[tid];
        CPA_COMMIT();
        CPA_WAIT0();
        __syncthreads();

        // ---- S = Q K^T (3-term bf16 split) ----
        float s[8][4];
        #pragma unroll
        for (int nt = 0; nt < 8; ++nt)
            #pragma unroll
            for (int c = 0; c < 4; ++c) s[nt][c] = 0.0f;

        #pragma unroll
        for (int kc = 0; kc < 8; ++kc) {
            uint32_t qh[4], ql[4];
            uint32_t qoff = (uint32_t)(arow * 256 + (((2 * kc + ag) ^ (arow & 7)) << 4));
            ldsm4(qh, sb + QH_OFF + qoff);
            ldsm4(ql, sb + QL_OFF + qoff);
            #pragma unroll
            for (int ntp = 0; ntp < 4; ++ntp) {
                uint32_t kh[4], kl[4];
                uint32_t koff = (uint32_t)((16 * ntp + brow) * 256 +
                                           (((2 * kc + bg) ^ (brow & 7)) << 4));
                ldsm4(kh, sb + KH_OFF + koff);
                ldsm4(kl, sb + KL_OFF + koff);
                mma16816(s[2 * ntp],     qh, kh[0], kh[1]);
                mma16816(s[2 * ntp],     qh, kl[0], kl[1]);
                mma16816(s[2 * ntp],     ql, kh[0], kh[1]);
                mma16816(s[2 * ntp + 1], qh, kh[2], kh[3]);
                mma16816(s[2 * ntp + 1], qh, kl[2], kl[3]);
                mma16816(s[2 * ntp + 1], ql, kh[2], kh[3]);
            }
        }

        // ---- scale + mask + online softmax (warp-local rows) ----
        float tm0 = -1e30f, tm1 = -1e30f;
        #pragma unroll
        for (int nt = 0; nt < 8; ++nt) {
            uchar2 mk = *reinterpret_cast<const uchar2*>(smem + MK_OFF + 8 * nt + ct2);
            float v0 = s[nt][0] * inv_scale; if (mk.x) v0 = -1e30f;
            float v1 = s[nt][1] * inv_scale; if (mk.y) v1 = -1e30f;
            float v2 = s[nt][2] * inv_scale; if (mk.x) v2 = -1e30f;
            float v3 = s[nt][3] * inv_scale; if (mk.y) v3 = -1e30f;
            s[nt][0] = v0; s[nt][1] = v1; s[nt][2] = v2; s[nt][3] = v3;
            tm0 = fmaxf(tm0, fmaxf(v0, v1));
            tm1 = fmaxf(tm1, fmaxf(v2, v3));
        }
        tm0 = fmaxf(tm0, __shfl_xor_sync(0xffffffffu, tm0, 1));
        tm0 = fmaxf(tm0, __shfl_xor_sync(0xffffffffu, tm0, 2));
        tm1 = fmaxf(tm1, __shfl_xor_sync(0xffffffffu, tm1, 1));
        tm1 = fmaxf(tm1, __shfl_xor_sync(0xffffffffu, tm1, 2));

        float mn0 = fmaxf(mst0, tm0), mn1 = fmaxf(mst1, tm1);
        float al0 = __expf(mst0 - mn0), al1 = __expf(mst1 - mn1);
        mst0 = mn0; mst1 = mn1;

        uint32_t ph[8][2], pl[8][2];
        float ps0 = 0.0f, ps1 = 0.0f;
        #pragma unroll
        for (int nt = 0; nt < 8; ++nt) {
            float p0 = __expf(s[nt][0] - mn0);
            float p1 = __expf(s[nt][1] - mn0);
            float p2 = __expf(s[nt][2] - mn1);
            float p3 = __expf(s[nt][3] - mn1);
            ps0 += p0 + p1; ps1 += p2 + p3;
            __nv_bfloat162 h0 = __float22bfloat162_rn(make_float2(p0, p1));
            __nv_bfloat162 h1 = __float22bfloat162_rn(make_float2(p2, p3));
            float2 d0 = __bfloat1622float2(h0);
            float2 d1 = __bfloat1622float2(h1);
            __nv_bfloat162 l0 = __float22bfloat162_rn(make_float2(p0 - d0.x, p1 - d0.y));
            __nv_bfloat162 l1 = __float22bfloat162_rn(make_float2(p2 - d1.x, p3 - d1.y));
            ph[nt][0] = reinterpret_cast<uint32_t&>(h0);
            ph[nt][1] = reinterpret_cast<uint32_t&>(h1);
            pl[nt][0] = reinterpret_cast<uint32_t&>(l0);
            pl[nt][1] = reinterpret_cast<uint32_t&>(l1);
        }
        ps0 += __shfl_xor_sync(0xffffffffu, ps0, 1);
        ps0 += __shfl_xor_sync(0xffffffffu, ps0, 2);
        ps1 += __shfl_xor_sync(0xffffffffu, ps1, 1);
        ps1 += __shfl_xor_sync(0xffffffffu, ps1, 2);
        lsum0 = lsum0 * al0 + ps0;
        lsum1 = lsum1 * al1 + ps1;

        #pragma unroll
        for (int nt = 0; nt < 16; ++nt) {
            o[nt][0] *= al0; o[nt][1] *= al0;
            o[nt][2] *= al1; o[nt][3] *= al1;
        }

        // ---- O += P V (3-term split; P frags straight from registers) ----
        #pragma unroll
        for (int kc = 0; kc < 4; ++kc) {
            uint32_t ah[4] = {ph[2 * kc][0], ph[2 * kc][1],
                              ph[2 * kc + 1][0], ph[2 * kc + 1][1]};
            uint32_t al[4] = {pl[2 * kc][0], pl[2 * kc][1],
                              pl[2 * kc + 1][0], pl[2 * kc + 1][1]};
            #pragma unroll
            for (int ntp = 0; ntp < 8; ++ntp) {
                uint32_t vh[4], vl[4];
                uint32_t voff = (uint32_t)((16 * kc + vrl) * 256 +
                                           (((2 * ntp + ag) ^ (vrl & 7)) << 4));
                ldsm4t(vh, sb + VH_OFF + voff);
                ldsm4t(vl, sb + VL_OFF + voff);
                mma16816(o[2 * ntp],     ah, vh[0], vh[1]);
                mma16816(o[2 * ntp],     ah, vl[0], vl[1]);
                mma16816(o[2 * ntp],     al, vh[0], vh[1]);
                mma16816(o[2 * ntp + 1], ah, vh[2], vh[3]);
                mma16816(o[2 * ntp + 1], ah, vl[2], vl[3]);
                mma16816(o[2 * ntp + 1], al, vh[2], vh[3]);
            }
        }
    }

    // ---- epilogue ----
    float il0 = 1.0f / lsum0, il1 = 1.0f / lsum1;
    int r0 = m0 + 16 * warp + gr;
    float* O0 = Og + ((size_t)b2048 + r0) * Dd + ct2;
    float* O1 = O0 + 8 * Dd;
    #pragma unroll
    for (int nt = 0; nt < 16; ++nt) {
        *reinterpret_cast<float2*>(O0 + 8 * nt) =
            make_float2(o[nt][0] * il0, o[nt][1] * il0);
        *reinterpret_cast<float2*>(O1 + 8 * nt) =
            make_float2(o[nt][2] * il1, o[nt][3] * il1);
    }
}

extern "C" void kernel_launch(void* const* d_in, const int* in_sizes, int n_in,
                              void* d_out, int out_size)
{
    const float* q = (const float*)d_in[0];
    const float* k = (const float*)d_in[1];
    const float* v = (const float*)d_in[2];
    const void*  m = d_in[3];
    float* out = (float*)d_out;

    detect_mask_mode_kernel<<<1, 256>>>((const unsigned int*)m);
    convert_mask_kernel<<<(Bb * Ss + 255) / 256, 256>>>(m);
    split_bf16_kernel<<<(N4 + 255) / 256, 256>>>(
        (const float4*)q, (const float4*)k, (const float4*)v);

    cudaFuncSetAttribute(attn_fwd_kernel,
                         cudaFuncAttributeMaxDynamicSharedMemorySize, SMEM_BYTES);
    dim3 grid(Ss / BM, Bb);
    attn_fwd_kernel<<<grid, NT, SMEM_BYTES>>>(out);
}

// round 9
// speedup vs baseline: 5.4127x; 1.7120x over previous
#include <cuda_runtime.h>
#include <cuda_bf16.h>
#include <cstdint>

namespace {
constexpr int Bb = 8, Ss = 2048, Dd = 128;
constexpr int BM = 64;    // query rows per CTA
constexpr int BN = 64;    // keys per tile
constexpr int NT = 128;   // 4 warps
constexpr int N4 = Bb * Ss * Dd / 4;   // float4 count per tensor

// smem byte offsets (bf16 tiles, 256B rows, XOR-swizzled 16B granules)
constexpr int QH_OFF = 0;        // 64 rows * 256B = 16384
constexpr int QL_OFF = 16384;
constexpr int KH_OFF = 32768;
constexpr int KL_OFF = 49152;
constexpr int VH_OFF = 65536;
constexpr int VL_OFF = 81920;
constexpr int SMEM_BYTES = 98304;
}

// split scratch + compaction tables (static device arrays: allocation-free)
__device__ uint2 gQh[N4], gQl[N4], gKh[N4], gKl[N4], gVh[N4], gVl[N4];
__device__ int   g_idx[Bb * Ss];
__device__ int   g_cnt[Bb];
__device__ unsigned char g_mask_bytes[Bb * Ss];
__device__ int   g_mask_mode;

// ---------------- prepass kernels ----------------
__global__ void detect_mask_mode_kernel(const unsigned int* __restrict__ M)
{
    __shared__ int ok4, ok2;
    if (threadIdx.x == 0) { ok4 = 1; ok2 = 1; }
    __syncthreads();
    int bad4 = 0, bad2 = 0;
    for (int i = threadIdx.x; i < 2048; i += blockDim.x) {
        unsigned int w = M[i];
        if (!(w == 0u || w == 1u || w == 0x3F800000u)) bad4 = 1;
        unsigned int lo = w & 0xFFFFu, hi = w >> 16;
        if (!((lo == 0u || lo == 0x3F80u) && (hi == 0u || hi == 0x3F80u))) bad2 = 1;
    }
    if (bad4) atomicAnd(&ok4, 0);
    if (bad2) atomicAnd(&ok2, 0);
    __syncthreads();
    if (threadIdx.x == 0) g_mask_mode = ok4 ? 2 : (ok2 ? 1 : 0);
}

__global__ void convert_mask_kernel(const void* __restrict__ M)
{
    int i = blockIdx.x * blockDim.x + threadIdx.x;
    if (i >= Bb * Ss) return;
    int mode = g_mask_mode;
    unsigned char masked;
    if (mode == 2)      masked = (((const unsigned int*)M)[i]   != 0u);
    else if (mode == 1) masked = (((const unsigned short*)M)[i] != 0u);
    else                masked = (((const unsigned char*)M)[i]  != 0u);
    g_mask_bytes[i] = masked;
}

// Deterministic per-batch compaction of unmasked key indices (prefix scan).
__global__ void compact_kernel()
{
    __shared__ int wsum[8], wbase[8];
    int b = blockIdx.x, t = threadIdx.x;
    int lane = t & 31, wp = t >> 5;
    unsigned long long w =
        reinterpret_cast<const unsigned long long*>(g_mask_bytes + b * Ss)[t];
    int cnt8 = 0, loc[8];
    #pragma unroll
    for (int k = 0; k < 8; ++k) {
        loc[k] = cnt8;
        cnt8 += (((w >> (8 * k)) & 0xFFull) == 0ull);
    }
    int inc = cnt8;
    #pragma unroll
    for (int off = 1; off < 32; off <<= 1) {
        int n = __shfl_up_sync(0xffffffffu, inc, off);
        if (lane >= off) inc += n;
    }
    if (lane == 31) wsum[wp] = inc;
    __syncthreads();
    if (t == 0) {
        int acc = 0;
        #pragma unroll
        for (int i = 0; i < 8; ++i) { wbase[i] = acc; acc += wsum[i]; }
        g_cnt[b] = acc;
    }
    __syncthreads();
    int base = wbase[wp] + inc - cnt8;
    #pragma unroll
    for (int k = 0; k < 8; ++k)
        if (((w >> (8 * k)) & 0xFFull) == 0ull)
            g_idx[b * Ss + base + loc[k]] = t * 8 + k;
}

__device__ __forceinline__ void split4(float4 f, uint2& hi, uint2& lo)
{
    __nv_bfloat162 h0 = __float22bfloat162_rn(make_float2(f.x, f.y));
    __nv_bfloat162 h1 = __float22bfloat162_rn(make_float2(f.z, f.w));
    float2 d0 = __bfloat1622float2(h0);
    float2 d1 = __bfloat1622float2(h1);
    __nv_bfloat162 l0 = __float22bfloat162_rn(make_float2(f.x - d0.x, f.y - d0.y));
    __nv_bfloat162 l1 = __float22bfloat162_rn(make_float2(f.z - d1.x, f.w - d1.y));
    hi.x = reinterpret_cast<uint32_t&>(h0); hi.y = reinterpret_cast<uint32_t&>(h1);
    lo.x = reinterpret_cast<uint32_t&>(l0); lo.y = reinterpret_cast<uint32_t&>(l1);
}

__global__ void split_q_kernel(const float4* __restrict__ Q)
{
    int i = blockIdx.x * blockDim.x + threadIdx.x;
    if (i >= N4) return;
    uint2 h, l;
    split4(Q[i], h, l); gQh[i] = h; gQl[i] = l;
}

// K,V gathered into compacted slot order, then hi/lo split.
__global__ void gather_split_kv_kernel(const float4* __restrict__ K,
                                       const float4* __restrict__ V)
{
    int i = blockIdx.x * blockDim.x + threadIdx.x;
    if (i >= N4) return;
    int c4 = i & 31;
    int s  = (i >> 5) & (Ss - 1);
    int b  = i >> 16;
    if (s >= g_cnt[b]) return;
    int j = g_idx[b * Ss + s];
    size_t src = (size_t)(b * Ss + j) * 32 + c4;
    uint2 h, l;
    split4(K[src], h, l); gKh[i] = h; gKl[i] = l;
    split4(V[src], h, l); gVh[i] = h; gVl[i] = l;
}

// ---------------- mma / ldmatrix / cp.async helpers ----------------
__device__ __forceinline__ void ldsm4(uint32_t* r, uint32_t addr)
{
    asm volatile("ldmatrix.sync.aligned.m8n8.x4.shared.b16 {%0,%1,%2,%3},[%4];"
        : "=r"(r[0]), "=r"(r[1]), "=r"(r[2]), "=r"(r[3]) : "r"(addr));
}
__device__ __forceinline__ void ldsm4t(uint32_t* r, uint32_t addr)
{
    asm volatile("ldmatrix.sync.aligned.m8n8.x4.trans.shared.b16 {%0,%1,%2,%3},[%4];"
        : "=r"(r[0]), "=r"(r[1]), "=r"(r[2]), "=r"(r[3]) : "r"(addr));
}
__device__ __forceinline__ void mma16816(float* c, const uint32_t* a,
                                         uint32_t b0, uint32_t b1)
{
    asm volatile("mma.sync.aligned.m16n8k16.row.col.f32.bf16.bf16.f32 "
        "{%0,%1,%2,%3},{%4,%5,%6,%7},{%8,%9},{%0,%1,%2,%3};"
        : "+f"(c[0]), "+f"(c[1]), "+f"(c[2]), "+f"(c[3])
        : "r"(a[0]), "r"(a[1]), "r"(a[2]), "r"(a[3]), "r"(b0), "r"(b1));
}
__device__ __forceinline__ void cpa16(uint32_t dst, const void* src)
{
    asm volatile("cp.async.cg.shared.global [%0], [%1], 16;"
                 :: "r"(dst), "l"(src) : "memory");
}
#define CPA_COMMIT() asm volatile("cp.async.commit_group;" ::: "memory")
#define CPA_WAIT0()  asm volatile("cp.async.wait_group 0;" ::: "memory")

// ---------------- main attention kernel ----------------
__global__ void __launch_bounds__(NT, 2)
attn_fwd_kernel(float* __restrict__ Og)
{
    extern __shared__ char smem[];
    uint32_t sb;
    asm("{.reg .u64 t; cvta.to.shared.u64 t, %1; cvt.u32.u64 %0, t;}"
        : "=r"(sb) : "l"(smem));

    const int b    = blockIdx.y;
    const int m0   = blockIdx.x * BM;
    const int tid  = threadIdx.x;
    const int lane = tid & 31;
    const int warp = tid >> 5;    // 0..3
    const int b2048 = b * Ss;
    const int cnt  = g_cnt[b];    // compacted key count for this batch

    const uint4* Qh4 = reinterpret_cast<const uint4*>(gQh);
    const uint4* Ql4 = reinterpret_cast<const uint4*>(gQl);
    const uint4* Kh4 = reinterpret_cast<const uint4*>(gKh);
    const uint4* Kl4 = reinterpret_cast<const uint4*>(gKl);
    const uint4* Vh4 = reinterpret_cast<const uint4*>(gVh);
    const uint4* Vl4 = reinterpret_cast<const uint4*>(gVl);

    // ---- stage Q tile (hi+lo) via cp.async, swizzled dst ----
    #pragma unroll
    for (int it = 0; it < 8; ++it) {
        int gi = it * NT + tid;          // 0..1023
        int row = gi >> 4, g = gi & 15;
        uint32_t sw16 = (uint32_t)(row * 16 + (g ^ (row & 7))) * 16u;
        size_t qidx = (size_t)(b2048 + m0 + row) * 16 + g;
        cpa16(sb + QH_OFF + sw16, Qh4 + qidx);
        cpa16(sb + QL_OFF + sw16, Ql4 + qidx);
    }
    CPA_COMMIT();

    // per-thread ldmatrix address patterns
    const int arow = 16 * warp + (lane & 15);          // A-frag row (Q)
    const int ag   = lane >> 4;                        // granule 0/1
    const int brow = (lane & 7) + ((lane & 16) >> 1);  // B-frag (K) row
    const int bg   = (lane >> 3) & 1;
    const int vrl  = lane & 15;                        // V-frag row
    const int ct2  = (lane & 3) * 2;                   // col-pair offset
    const int gr   = lane >> 2;                        // row group

    float o[16][4];
    #pragma unroll
    for (int nt = 0; nt < 16; ++nt)
        #pragma unroll
        for (int c = 0; c < 4; ++c) o[nt][c] = 0.0f;
    float mst0 = -1e30f, mst1 = -1e30f, lsum0 = 0.0f, lsum1 = 0.0f;
    const float inv_scale = 0.08838834764831845f;

    for (int n0 = 0; n0 < cnt; n0 += BN) {
        __syncthreads();   // previous tile's reads done

        // ---- stage K,V (hi+lo) via cp.async ----
        #pragma unroll
        for (int it = 0; it < 8; ++it) {
            int gi = it * NT + tid;      // 0..1023
            int row = gi >> 4, g = gi & 15;
            uint32_t sw16 = (uint32_t)(row * 16 + (g ^ (row & 7))) * 16u;
            size_t gidx = (size_t)(b2048 + n0 + row) * 16 + g;
            cpa16(sb + KH_OFF + sw16, Kh4 + gidx);
            cpa16(sb + KL_OFF + sw16, Kl4 + gidx);
            cpa16(sb + VH_OFF + sw16, Vh4 + gidx);
            cpa16(sb + VL_OFF + sw16, Vl4 + gidx);
        }
        CPA_COMMIT();
        CPA_WAIT0();
        __syncthreads();

        // ---- S = Q K^T (3-term bf16 split) ----
        float s[8][4];
        #pragma unroll
        for (int nt = 0; nt < 8; ++nt)
            #pragma unroll
            for (int c = 0; c < 4; ++c) s[nt][c] = 0.0f;

        #pragma unroll
        for (int kc = 0; kc < 8; ++kc) {
            uint32_t qh[4], ql[4];
            uint32_t qoff = (uint32_t)(arow * 256 + (((2 * kc + ag) ^ (arow & 7)) << 4));
            ldsm4(qh, sb + QH_OFF + qoff);
            ldsm4(ql, sb + QL_OFF + qoff);
            #pragma unroll
            for (int ntp = 0; ntp < 4; ++ntp) {
                uint32_t kh[4], kl[4];
                uint32_t koff = (uint32_t)((16 * ntp + brow) * 256 +
                                           (((2 * kc + bg) ^ (brow & 7)) << 4));
                ldsm4(kh, sb + KH_OFF + koff);
                ldsm4(kl, sb + KL_OFF + koff);
                mma16816(s[2 * ntp],     qh, kh[0], kh[1]);
                mma16816(s[2 * ntp],     qh, kl[0], kl[1]);
                mma16816(s[2 * ntp],     ql, kh[0], kh[1]);
                mma16816(s[2 * ntp + 1], qh, kh[2], kh[3]);
                mma16816(s[2 * ntp + 1], qh, kl[2], kl[3]);
                mma16816(s[2 * ntp + 1], ql, kh[2], kh[3]);
            }
        }

        // ---- scale + tail-predicate + online softmax (warp-local rows) ----
        float tm0 = -1e30f, tm1 = -1e30f;
        #pragma unroll
        for (int nt = 0; nt < 8; ++nt) {
            int jb = n0 + 8 * nt + ct2;        // key index of cols 0/2
            bool mx = jb >= cnt, my = (jb + 1) >= cnt;
            float v0 = s[nt][0] * inv_scale; if (mx) v0 = -1e30f;
            float v1 = s[nt][1] * inv_scale; if (my) v1 = -1e30f;
            float v2 = s[nt][2] * inv_scale; if (mx) v2 = -1e30f;
            float v3 = s[nt][3] * inv_scale; if (my) v3 = -1e30f;
            s[nt][0] = v0; s[nt][1] = v1; s[nt][2] = v2; s[nt][3] = v3;
            tm0 = fmaxf(tm0, fmaxf(v0, v1));
            tm1 = fmaxf(tm1, fmaxf(v2, v3));
        }
        tm0 = fmaxf(tm0, __shfl_xor_sync(0xffffffffu, tm0, 1));
        tm0 = fmaxf(tm0, __shfl_xor_sync(0xffffffffu, tm0, 2));
        tm1 = fmaxf(tm1, __shfl_xor_sync(0xffffffffu, tm1, 1));
        tm1 = fmaxf(tm1, __shfl_xor_sync(0xffffffffu, tm1, 2));

        float mn0 = fmaxf(mst0, tm0), mn1 = fmaxf(mst1, tm1);
        float al0 = __expf(mst0 - mn0), al1 = __expf(mst1 - mn1);
        mst0 = mn0; mst1 = mn1;

        uint32_t ph[8][2], pl[8][2];
        float ps0 = 0.0f, ps1 = 0.0f;
        #pragma unroll
        for (int nt = 0; nt < 8; ++nt) {
            float p0 = __expf(s[nt][0] - mn0);
            float p1 = __expf(s[nt][1] - mn0);
            float p2 = __expf(s[nt][2] - mn1);
            float p3 = __expf(s[nt][3] - mn1);
            ps0 += p0 + p1; ps1 += p2 + p3;
            __nv_bfloat162 h0 = __float22bfloat162_rn(make_float2(p0, p1));
            __nv_bfloat162 h1 = __float22bfloat162_rn(make_float2(p2, p3));
            float2 d0 = __bfloat1622float2(h0);
            float2 d1 = __bfloat1622float2(h1);
            __nv_bfloat162 l0 = __float22bfloat162_rn(make_float2(p0 - d0.x, p1 - d0.y));
            __nv_bfloat162 l1 = __float22bfloat162_rn(make_float2(p2 - d1.x, p3 - d1.y));
            ph[nt][0] = reinterpret_cast<uint32_t&>(h0);
            ph[nt][1] = reinterpret_cast<uint32_t&>(h1);
            pl[nt][0] = reinterpret_cast<uint32_t&>(l0);
            pl[nt][1] = reinterpret_cast<uint32_t&>(l1);
        }
        ps0 += __shfl_xor_sync(0xffffffffu, ps0, 1);
        ps0 += __shfl_xor_sync(0xffffffffu, ps0, 2);
        ps1 += __shfl_xor_sync(0xffffffffu, ps1, 1);
        ps1 += __shfl_xor_sync(0xffffffffu, ps1, 2);
        lsum0 = lsum0 * al0 + ps0;
        lsum1 = lsum1 * al1 + ps1;

        #pragma unroll
        for (int nt = 0; nt < 16; ++nt) {
            o[nt][0] *= al0; o[nt][1] *= al0;
            o[nt][2] *= al1; o[nt][3] *= al1;
        }

        // ---- O += P V (3-term split; P frags straight from registers) ----
        #pragma unroll
        for (int kc = 0; kc < 4; ++kc) {
            uint32_t ah[4] = {ph[2 * kc][0], ph[2 * kc][1],
                              ph[2 * kc + 1][0], ph[2 * kc + 1][1]};
            uint32_t al[4] = {pl[2 * kc][0], pl[2 * kc][1],
                              pl[2 * kc + 1][0], pl[2 * kc + 1][1]};
            #pragma unroll
            for (int ntp = 0; ntp < 8; ++ntp) {
                uint32_t vh[4], vl[4];
                uint32_t voff = (uint32_t)((16 * kc + vrl) * 256 +
                                           (((2 * ntp + ag) ^ (vrl & 7)) << 4));
                ldsm4t(vh, sb + VH_OFF + voff);
                ldsm4t(vl, sb + VL_OFF + voff);
                mma16816(o[2 * ntp],     ah, vh[0], vh[1]);
                mma16816(o[2 * ntp],     ah, vl[0], vl[1]);
                mma16816(o[2 * ntp],     al, vh[0], vh[1]);
                mma16816(o[2 * ntp + 1], ah, vh[2], vh[3]);
                mma16816(o[2 * ntp + 1], ah, vl[2], vl[3]);
                mma16816(o[2 * ntp + 1], al, vh[2], vh[3]);
            }
        }
    }

    // ---- epilogue ----
    float il0 = 1.0f / lsum0, il1 = 1.0f / lsum1;
    int r0 = m0 + 16 * warp + gr;
    float* O0 = Og + ((size_t)b2048 + r0) * Dd + ct2;
    float* O1 = O0 + 8 * Dd;
    #pragma unroll
    for (int nt = 0; nt < 16; ++nt) {
        *reinterpret_cast<float2*>(O0 + 8 * nt) =
            make_float2(o[nt][0] * il0, o[nt][1] * il0);
        *reinterpret_cast<float2*>(O1 + 8 * nt) =
            make_float2(o[nt][2] * il1, o[nt][3] * il1);
    }
}

extern "C" void kernel_launch(void* const* d_in, const int* in_sizes, int n_in,
                              void* d_out, int out_size)
{
    const float* q = (const float*)d_in[0];
    const float* k = (const float*)d_in[1];
    const float* v = (const float*)d_in[2];
    const void*  m = d_in[3];
    float* out = (float*)d_out;

    detect_mask_mode_kernel<<<1, 256>>>((const unsigned int*)m);
    convert_mask_kernel<<<(Bb * Ss + 255) / 256, 256>>>(m);
    compact_kernel<<<Bb, 256>>>();
    split_q_kernel<<<(N4 + 255) / 256, 256>>>((const float4*)q);
    gather_split_kv_kernel<<<(N4 + 255) / 256, 256>>>(
        (const float4*)k, (const float4*)v);

    cudaFuncSetAttribute(attn_fwd_kernel,
                         cudaFuncAttributeMaxDynamicSharedMemorySize, SMEM_BYTES);
    dim3 grid(Ss / BM, Bb);
    attn_fwd_kernel<<<grid, NT, SMEM_BYTES>>>(out);
}

// round 10
// speedup vs baseline: 5.7961x; 1.0708x over previous
#include <cuda_runtime.h>
#include <cuda_bf16.h>
#include <cstdint>

namespace {
constexpr int Bb = 8, Ss = 2048, Dd = 128;
constexpr int BM = 64;    // query rows per CTA
constexpr int BN = 64;    // keys per tile
constexpr int NT = 128;   // 4 warps
constexpr int N4 = Bb * Ss * Dd / 4;   // float4 count per tensor

// smem byte offsets (bf16 tiles, 256B rows, XOR-swizzled 16B granules)
constexpr int QH_OFF = 0;        // 64 rows * 256B = 16384
constexpr int QL_OFF = 16384;
constexpr int KH_OFF = 32768;
constexpr int KL_OFF = 49152;
constexpr int VH_OFF = 65536;
constexpr int VL_OFF = 81920;
constexpr int SMEM_BYTES = 98304;
}

// split scratch + compaction tables (static device arrays: allocation-free)
__device__ uint2 gQh[N4], gQl[N4], gKh[N4], gKl[N4], gVh[N4], gVl[N4];
__device__ int   g_idx[Bb * Ss];
__device__ int   g_cnt[Bb];

// ---------------- fused prepass 1: detect + convert + compact ----------------
__global__ void mask_prep_kernel(const void* __restrict__ M)
{
    __shared__ int ok4, ok2;
    __shared__ unsigned char mb[Ss];
    __shared__ int wsum[8], wbase[8];

    int b = blockIdx.x, t = threadIdx.x;
    int lane = t & 31, wp = t >> 5;

    if (t == 0) { ok4 = 1; ok2 = 1; }
    __syncthreads();

    // dtype detection from a 2KB sample (dtype is global, any batch works)
    int bad4 = 0, bad2 = 0;
    const unsigned int* Mw = (const unsigned int*)M;
    for (int i = t; i < 512; i += 256) {
        unsigned int w = Mw[i];
        if (!(w == 0u || w == 1u || w == 0x3F800000u)) bad4 = 1;
        unsigned int lo = w & 0xFFFFu, hi = w >> 16;
        if (!((lo == 0u || lo == 0x3F80u) && (hi == 0u || hi == 0x3F80u))) bad2 = 1;
    }
    if (bad4) atomicAnd(&ok4, 0);
    if (bad2) atomicAnd(&ok2, 0);
    __syncthreads();
    int mode = ok4 ? 2 : (ok2 ? 1 : 0);

    // convert this batch's 2048 mask elements into smem bytes
    #pragma unroll
    for (int k = 0; k < 8; ++k) {
        int e = t * 8 + k;
        int gi = b * Ss + e;
        unsigned char v;
        if (mode == 2)      v = (((const unsigned int*)M)[gi]   != 0u);
        else if (mode == 1) v = (((const unsigned short*)M)[gi] != 0u);
        else                v = (((const unsigned char*)M)[gi]  != 0u);
        mb[e] = v;
    }
    __syncthreads();

    // deterministic prefix-scan compaction of unmasked indices
    unsigned long long w = reinterpret_cast<const unsigned long long*>(mb)[t];
    int cnt8 = 0, loc[8];
    #pragma unroll
    for (int k = 0; k < 8; ++k) {
        loc[k] = cnt8;
        cnt8 += (((w >> (8 * k)) & 0xFFull) == 0ull);
    }
    int inc = cnt8;
    #pragma unroll
    for (int off = 1; off < 32; off <<= 1) {
        int n = __shfl_up_sync(0xffffffffu, inc, off);
        if (lane >= off) inc += n;
    }
    if (lane == 31) wsum[wp] = inc;
    __syncthreads();
    if (t == 0) {
        int acc = 0;
        #pragma unroll
        for (int i = 0; i < 8; ++i) { wbase[i] = acc; acc += wsum[i]; }
        g_cnt[b] = acc;
    }
    __syncthreads();
    int base = wbase[wp] + inc - cnt8;
    #pragma unroll
    for (int k = 0; k < 8; ++k)
        if (((w >> (8 * k)) & 0xFFull) == 0ull)
            g_idx[b * Ss + base + loc[k]] = t * 8 + k;
}

// ---------------- fused prepass 2: split Q + gather-split K,V ----------------
__device__ __forceinline__ void split4(float4 f, uint2& hi, uint2& lo)
{
    __nv_bfloat162 h0 = __float22bfloat162_rn(make_float2(f.x, f.y));
    __nv_bfloat162 h1 = __float22bfloat162_rn(make_float2(f.z, f.w));
    float2 d0 = __bfloat1622float2(h0);
    float2 d1 = __bfloat1622float2(h1);
    __nv_bfloat162 l0 = __float22bfloat162_rn(make_float2(f.x - d0.x, f.y - d0.y));
    __nv_bfloat162 l1 = __float22bfloat162_rn(make_float2(f.z - d1.x, f.w - d1.y));
    hi.x = reinterpret_cast<uint32_t&>(h0); hi.y = reinterpret_cast<uint32_t&>(h1);
    lo.x = reinterpret_cast<uint32_t&>(l0); lo.y = reinterpret_cast<uint32_t&>(l1);
}

__global__ void split_gather_kernel(const float4* __restrict__ Q,
                                    const float4* __restrict__ K,
                                    const float4* __restrict__ V)
{
    int i = blockIdx.x * blockDim.x + threadIdx.x;
    if (i >= N4) return;
    uint2 h, l;
    split4(Q[i], h, l); gQh[i] = h; gQl[i] = l;

    int c4 = i & 31;
    int s  = (i >> 5) & (Ss - 1);
    int b  = i >> 16;
    if (s >= g_cnt[b]) return;
    int j = g_idx[b * Ss + s];
    size_t src = (size_t)(b * Ss + j) * 32 + c4;
    split4(K[src], h, l); gKh[i] = h; gKl[i] = l;
    split4(V[src], h, l); gVh[i] = h; gVl[i] = l;
}

// ---------------- mma / ldmatrix / cp.async helpers ----------------
__device__ __forceinline__ void ldsm4(uint32_t* r, uint32_t addr)
{
    asm volatile("ldmatrix.sync.aligned.m8n8.x4.shared.b16 {%0,%1,%2,%3},[%4];"
        : "=r"(r[0]), "=r"(r[1]), "=r"(r[2]), "=r"(r[3]) : "r"(addr));
}
__device__ __forceinline__ void ldsm4t(uint32_t* r, uint32_t addr)
{
    asm volatile("ldmatrix.sync.aligned.m8n8.x4.trans.shared.b16 {%0,%1,%2,%3},[%4];"
        : "=r"(r[0]), "=r"(r[1]), "=r"(r[2]), "=r"(r[3]) : "r"(addr));
}
__device__ __forceinline__ void mma16816(float* c, const uint32_t* a,
                                         uint32_t b0, uint32_t b1)
{
    asm volatile("mma.sync.aligned.m16n8k16.row.col.f32.bf16.bf16.f32 "
        "{%0,%1,%2,%3},{%4,%5,%6,%7},{%8,%9},{%0,%1,%2,%3};"
        : "+f"(c[0]), "+f"(c[1]), "+f"(c[2]), "+f"(c[3])
        : "r"(a[0]), "r"(a[1]), "r"(a[2]), "r"(a[3]), "r"(b0), "r"(b1));
}
__device__ __forceinline__ void cpa16(uint32_t dst, const void* src)
{
    asm volatile("cp.async.cg.shared.global [%0], [%1], 16;"
                 :: "r"(dst), "l"(src) : "memory");
}
#define CPA_COMMIT() asm volatile("cp.async.commit_group;" ::: "memory")
#define CPA_WAIT0()  asm volatile("cp.async.wait_group 0;" ::: "memory")

// ---------------- main attention kernel ----------------
__global__ void __launch_bounds__(NT, 2)
attn_fwd_kernel(float* __restrict__ Og)
{
    extern __shared__ char smem[];
    uint32_t sb;
    asm("{.reg .u64 t; cvta.to.shared.u64 t, %1; cvt.u32.u64 %0, t;}"
        : "=r"(sb) : "l"(smem));

    const int b    = blockIdx.y;
    const int m0   = blockIdx.x * BM;
    const int tid  = threadIdx.x;
    const int lane = tid & 31;
    const int warp = tid >> 5;    // 0..3
    const int b2048 = b * Ss;
    const int cnt  = g_cnt[b];    // compacted key count for this batch

    const uint4* Qh4 = reinterpret_cast<const uint4*>(gQh);
    const uint4* Ql4 = reinterpret_cast<const uint4*>(gQl);
    const uint4* Kh4 = reinterpret_cast<const uint4*>(gKh);
    const uint4* Kl4 = reinterpret_cast<const uint4*>(gKl);
    const uint4* Vh4 = reinterpret_cast<const uint4*>(gVh);
    const uint4* Vl4 = reinterpret_cast<const uint4*>(gVl);

    // ---- stage Q tile (hi+lo) via cp.async, swizzled dst ----
    #pragma unroll
    for (int it = 0; it < 8; ++it) {
        int gi = it * NT + tid;          // 0..1023
        int row = gi >> 4, g = gi & 15;
        uint32_t sw16 = (uint32_t)(row * 16 + (g ^ (row & 7))) * 16u;
        size_t qidx = (size_t)(b2048 + m0 + row) * 16 + g;
        cpa16(sb + QH_OFF + sw16, Qh4 + qidx);
        cpa16(sb + QL_OFF + sw16, Ql4 + qidx);
    }
    // ---- stage K0,V0 ----
    #pragma unroll
    for (int it = 0; it < 8; ++it) {
        int gi = it * NT + tid;
        int row = gi >> 4, g = gi & 15;
        uint32_t sw16 = (uint32_t)(row * 16 + (g ^ (row & 7))) * 16u;
        size_t gidx = (size_t)b2048 * 16 + (size_t)gi;
        cpa16(sb + KH_OFF + sw16, Kh4 + gidx);
        cpa16(sb + KL_OFF + sw16, Kl4 + gidx);
        cpa16(sb + VH_OFF + sw16, Vh4 + gidx);
        cpa16(sb + VL_OFF + sw16, Vl4 + gidx);
    }
    CPA_COMMIT();

    // per-thread ldmatrix address patterns
    const int arow = 16 * warp + (lane & 15);          // A-frag row (Q)
    const int ag   = lane >> 4;                        // granule 0/1
    const int brow = (lane & 7) + ((lane & 16) >> 1);  // B-frag (K) row
    const int bg   = (lane >> 3) & 1;
    const int vrl  = lane & 15;                        // V-frag row
    const int ct2  = (lane & 3) * 2;                   // col-pair offset
    const int gr   = lane >> 2;                        // row group

    float o[16][4];
    #pragma unroll
    for (int nt = 0; nt < 16; ++nt)
        #pragma unroll
        for (int c = 0; c < 4; ++c) o[nt][c] = 0.0f;
    float mst0 = -1e30f, mst1 = -1e30f, lsum0 = 0.0f, lsum1 = 0.0f;
    const float inv_scale = 0.08838834764831845f;

    for (int n0 = 0; n0 < cnt; n0 += BN) {
        const bool more = (n0 + BN) < cnt;

        CPA_WAIT0();
        __syncthreads();   // K/V tiles visible; prev readers done

        // ---- S = Q K^T (3-term bf16 split) ----
        float s[8][4];
        #pragma unroll
        for (int nt = 0; nt < 8; ++nt)
            #pragma unroll
            for (int c = 0; c < 4; ++c) s[nt][c] = 0.0f;

        #pragma unroll
        for (int kc = 0; kc < 8; ++kc) {
            uint32_t qh[4], ql[4];
            uint32_t qoff = (uint32_t)(arow * 256 + (((2 * kc + ag) ^ (arow & 7)) << 4));
            ldsm4(qh, sb + QH_OFF + qoff);
            ldsm4(ql, sb + QL_OFF + qoff);
            #pragma unroll
            for (int ntp = 0; ntp < 4; ++ntp) {
                uint32_t kh[4], kl[4];
                uint32_t koff = (uint32_t)((16 * ntp + brow) * 256 +
                                           (((2 * kc + bg) ^ (brow & 7)) << 4));
                ldsm4(kh, sb + KH_OFF + koff);
                ldsm4(kl, sb + KL_OFF + koff);
                mma16816(s[2 * ntp],     qh, kh[0], kh[1]);
                mma16816(s[2 * ntp],     qh, kl[0], kl[1]);
                mma16816(s[2 * ntp],     ql, kh[0], kh[1]);
                mma16816(s[2 * ntp + 1], qh, kh[2], kh[3]);
                mma16816(s[2 * ntp + 1], qh, kl[2], kl[3]);
                mma16816(s[2 * ntp + 1], ql, kh[2], kh[3]);
            }
        }
        __syncthreads();   // all warps done reading K buffers

        // ---- prefetch K(t+1) while softmax+PV run ----
        if (more) {
            #pragma unroll
            for (int it = 0; it < 8; ++it) {
                int gi = it * NT + tid;
                int row = gi >> 4, g = gi & 15;
                uint32_t sw16 = (uint32_t)(row * 16 + (g ^ (row & 7))) * 16u;
                size_t gidx = (size_t)(b2048 + n0 + BN + row) * 16 + g;
                cpa16(sb + KH_OFF + sw16, Kh4 + gidx);
                cpa16(sb + KL_OFF + sw16, Kl4 + gidx);
            }
            CPA_COMMIT();
        }

        // ---- scale + tail-predicate + online softmax (warp-local rows) ----
        float tm0 = -1e30f, tm1 = -1e30f;
        #pragma unroll
        for (int nt = 0; nt < 8; ++nt) {
            int jb = n0 + 8 * nt + ct2;        // key index of cols 0/2
            bool mx = jb >= cnt, my = (jb + 1) >= cnt;
            float v0 = s[nt][0] * inv_scale; if (mx) v0 = -1e30f;
            float v1 = s[nt][1] * inv_scale; if (my) v1 = -1e30f;
            float v2 = s[nt][2] * inv_scale; if (mx) v2 = -1e30f;
            float v3 = s[nt][3] * inv_scale; if (my) v3 = -1e30f;
            s[nt][0] = v0; s[nt][1] = v1; s[nt][2] = v2; s[nt][3] = v3;
            tm0 = fmaxf(tm0, fmaxf(v0, v1));
            tm1 = fmaxf(tm1, fmaxf(v2, v3));
        }
        tm0 = fmaxf(tm0, __shfl_xor_sync(0xffffffffu, tm0, 1));
        tm0 = fmaxf(tm0, __shfl_xor_sync(0xffffffffu, tm0, 2));
        tm1 = fmaxf(tm1, __shfl_xor_sync(0xffffffffu, tm1, 1));
        tm1 = fmaxf(tm1, __shfl_xor_sync(0xffffffffu, tm1, 2));

        float mn0 = fmaxf(mst0, tm0), mn1 = fmaxf(mst1, tm1);
        float al0 = __expf(mst0 - mn0), al1 = __expf(mst1 - mn1);
        mst0 = mn0; mst1 = mn1;

        uint32_t ph[8][2], pl[8][2];
        float ps0 = 0.0f, ps1 = 0.0f;
        #pragma unroll
        for (int nt = 0; nt < 8; ++nt) {
            float p0 = __expf(s[nt][0] - mn0);
            float p1 = __expf(s[nt][1] - mn0);
            float p2 = __expf(s[nt][2] - mn1);
            float p3 = __expf(s[nt][3] - mn1);
            ps0 += p0 + p1; ps1 += p2 + p3;
            __nv_bfloat162 h0 = __float22bfloat162_rn(make_float2(p0, p1));
            __nv_bfloat162 h1 = __float22bfloat162_rn(make_float2(p2, p3));
            float2 d0 = __bfloat1622float2(h0);
            float2 d1 = __bfloat1622float2(h1);
            __nv_bfloat162 l0 = __float22bfloat162_rn(make_float2(p0 - d0.x, p1 - d0.y));
            __nv_bfloat162 l1 = __float22bfloat162_rn(make_float2(p2 - d1.x, p3 - d1.y));
            ph[nt][0] = reinterpret_cast<uint32_t&>(h0);
            ph[nt][1] = reinterpret_cast<uint32_t&>(h1);
            pl[nt][0] = reinterpret_cast<uint32_t&>(l0);
            pl[nt][1] = reinterpret_cast<uint32_t&>(l1);
        }
        ps0 += __shfl_xor_sync(0xffffffffu, ps0, 1);
        ps0 += __shfl_xor_sync(0xffffffffu, ps0, 2);
        ps1 += __shfl_xor_sync(0xffffffffu, ps1, 1);
        ps1 += __shfl_xor_sync(0xffffffffu, ps1, 2);
        lsum0 = lsum0 * al0 + ps0;
        lsum1 = lsum1 * al1 + ps1;

        #pragma unroll
        for (int nt = 0; nt < 16; ++nt) {
            o[nt][0] *= al0; o[nt][1] *= al0;
            o[nt][2] *= al1; o[nt][3] *= al1;
        }

        // ---- O += P V (3-term split; P frags straight from registers) ----
        #pragma unroll
        for (int kc = 0; kc < 4; ++kc) {
            uint32_t ah[4] = {ph[2 * kc][0], ph[2 * kc][1],
                              ph[2 * kc + 1][0], ph[2 * kc + 1][1]};
            uint32_t al[4] = {pl[2 * kc][0], pl[2 * kc][1],
                              pl[2 * kc + 1][0], pl[2 * kc + 1][1]};
            #pragma unroll
            for (int ntp = 0; ntp < 8; ++ntp) {
                uint32_t vh[4], vl[4];
                uint32_t voff = (uint32_t)((16 * kc + vrl) * 256 +
                                           (((2 * ntp + ag) ^ (vrl & 7)) << 4));
                ldsm4t(vh, sb + VH_OFF + voff);
                ldsm4t(vl, sb + VL_OFF + voff);
                mma16816(o[2 * ntp],     ah, vh[0], vh[1]);
                mma16816(o[2 * ntp],     ah, vl[0], vl[1]);
                mma16816(o[2 * ntp],     al, vh[0], vh[1]);
                mma16816(o[2 * ntp + 1], ah, vh[2], vh[3]);
                mma16816(o[2 * ntp + 1], ah, vl[2], vl[3]);
                mma16816(o[2 * ntp + 1], al, vh[2], vh[3]);
            }
        }
        __syncthreads();   // all warps done reading V buffers

        // ---- prefetch V(t+1) ----
        if (more) {
            #pragma unroll
            for (int it = 0; it < 8; ++it) {
                int gi = it * NT + tid;
                int row = gi >> 4, g = gi & 15;
                uint32_t sw16 = (uint32_t)(row * 16 + (g ^ (row & 7))) * 16u;
                size_t gidx = (size_t)(b2048 + n0 + BN + row) * 16 + g;
                cpa16(sb + VH_OFF + sw16, Vh4 + gidx);
                cpa16(sb + VL_OFF + sw16, Vl4 + gidx);
            }
            CPA_COMMIT();
        }
    }

    // ---- epilogue ----
    float il0 = 1.0f / lsum0, il1 = 1.0f / lsum1;
    int r0 = m0 + 16 * warp + gr;
    float* O0 = Og + ((size_t)b2048 + r0) * Dd + ct2;
    float* O1 = O0 + 8 * Dd;
    #pragma unroll
    for (int nt = 0; nt < 16; ++nt) {
        *reinterpret_cast<float2*>(O0 + 8 * nt) =
            make_float2(o[nt][0] * il0, o[nt][1] * il0);
        *reinterpret_cast<float2*>(O1 + 8 * nt) =
            make_float2(o[nt][2] * il1, o[nt][3] * il1);
    }
}

extern "C" void kernel_launch(void* const* d_in, const int* in_sizes, int n_in,
                              void* d_out, int out_size)
{
    const float* q = (const float*)d_in[0];
    const float* k = (const float*)d_in[1];
    const float* v = (const float*)d_in[2];
    const void*  m = d_in[3];
    float* out = (float*)d_out;

    mask_prep_kernel<<<Bb, 256>>>(m);
    split_gather_kernel<<<(N4 + 255) / 256, 256>>>(
        (const float4*)q, (const float4*)k, (const float4*)v);

    cudaFuncSetAttribute(attn_fwd_kernel,
                         cudaFuncAttributeMaxDynamicSharedMemorySize, SMEM_BYTES);
    dim3 grid(Ss / BM, Bb);
    attn_fwd_kernel<<<grid, NT, SMEM_BYTES>>>(out);
}

// round 11
// speedup vs baseline: 6.0440x; 1.0428x over previous
#include <cuda_runtime.h>
#include <cuda_bf16.h>
#include <cstdint>

namespace {
constexpr int Bb = 8, Ss = 2048, Dd = 128;
constexpr int BM = 64;    // query rows per CTA
constexpr int BN = 32;    // keys per tile (double-buffered)
constexpr int NT = 128;   // 4 warps
constexpr int N4 = Bb * Ss * Dd / 4;   // float4 count per tensor

// smem: Q images + double-buffered K/V images (256B rows, XOR-swizzled 16B granules)
constexpr int QH_OFF = 0;        // 64 rows * 256B
constexpr int QL_OFF = 16384;
constexpr int K_OFF  = 32768;    // [buf][hi/lo] 4 x 8KB
constexpr int V_OFF  = 65536;    // [buf][hi/lo] 4 x 8KB
constexpr int SMEM_BYTES = 98304;
}

// split scratch + compaction tables (static device arrays: allocation-free)
__device__ uint2 gKh[N4], gKl[N4], gVh[N4], gVl[N4];
__device__ int   g_idx[Bb * Ss];
__device__ int   g_cnt[Bb];

// ---------------- prepass 1: detect + convert + compact ----------------
__global__ void mask_prep_kernel(const void* __restrict__ M)
{
    __shared__ int ok4, ok2;
    __shared__ unsigned char mb[Ss];
    __shared__ int wsum[8], wbase[8];

    int b = blockIdx.x, t = threadIdx.x;
    int lane = t & 31, wp = t >> 5;

    if (t == 0) { ok4 = 1; ok2 = 1; }
    __syncthreads();

    int bad4 = 0, bad2 = 0;
    const unsigned int* Mw = (const unsigned int*)M;
    for (int i = t; i < 512; i += 256) {
        unsigned int w = Mw[i];
        if (!(w == 0u || w == 1u || w == 0x3F800000u)) bad4 = 1;
        unsigned int lo = w & 0xFFFFu, hi = w >> 16;
        if (!((lo == 0u || lo == 0x3F80u) && (hi == 0u || hi == 0x3F80u))) bad2 = 1;
    }
    if (bad4) atomicAnd(&ok4, 0);
    if (bad2) atomicAnd(&ok2, 0);
    __syncthreads();
    int mode = ok4 ? 2 : (ok2 ? 1 : 0);

    #pragma unroll
    for (int k = 0; k < 8; ++k) {
        int e = t * 8 + k;
        int gi = b * Ss + e;
        unsigned char v;
        if (mode == 2)      v = (((const unsigned int*)M)[gi]   != 0u);
        else if (mode == 1) v = (((const unsigned short*)M)[gi] != 0u);
        else                v = (((const unsigned char*)M)[gi]  != 0u);
        mb[e] = v;
    }
    __syncthreads();

    unsigned long long w = reinterpret_cast<const unsigned long long*>(mb)[t];
    int cnt8 = 0, loc[8];
    #pragma unroll
    for (int k = 0; k < 8; ++k) {
        loc[k] = cnt8;
        cnt8 += (((w >> (8 * k)) & 0xFFull) == 0ull);
    }
    int inc = cnt8;
    #pragma unroll
    for (int off = 1; off < 32; off <<= 1) {
        int n = __shfl_up_sync(0xffffffffu, inc, off);
        if (lane >= off) inc += n;
    }
    if (lane == 31) wsum[wp] = inc;
    __syncthreads();
    if (t == 0) {
        int acc = 0;
        #pragma unroll
        for (int i = 0; i < 8; ++i) { wbase[i] = acc; acc += wsum[i]; }
        g_cnt[b] = acc;
    }
    __syncthreads();
    int base = wbase[wp] + inc - cnt8;
    #pragma unroll
    for (int k = 0; k < 8; ++k)
        if (((w >> (8 * k)) & 0xFFull) == 0ull)
            g_idx[b * Ss + base + loc[k]] = t * 8 + k;
}

// ---------------- prepass 2: gather-split K,V only ----------------
__device__ __forceinline__ void split4(float4 f, uint2& hi, uint2& lo)
{
    __nv_bfloat162 h0 = __float22bfloat162_rn(make_float2(f.x, f.y));
    __nv_bfloat162 h1 = __float22bfloat162_rn(make_float2(f.z, f.w));
    float2 d0 = __bfloat1622float2(h0);
    float2 d1 = __bfloat1622float2(h1);
    __nv_bfloat162 l0 = __float22bfloat162_rn(make_float2(f.x - d0.x, f.y - d0.y));
    __nv_bfloat162 l1 = __float22bfloat162_rn(make_float2(f.z - d1.x, f.w - d1.y));
    hi.x = reinterpret_cast<uint32_t&>(h0); hi.y = reinterpret_cast<uint32_t&>(h1);
    lo.x = reinterpret_cast<uint32_t&>(l0); lo.y = reinterpret_cast<uint32_t&>(l1);
}

__global__ void kv_prep_kernel(const float4* __restrict__ K,
                               const float4* __restrict__ V)
{
    int i = blockIdx.x * blockDim.x + threadIdx.x;
    if (i >= N4) return;
    int c4 = i & 31;
    int s  = (i >> 5) & (Ss - 1);
    int b  = i >> 16;
    if (s >= g_cnt[b]) return;
    int j = g_idx[b * Ss + s];
    size_t src = (size_t)(b * Ss + j) * 32 + c4;
    uint2 h, l;
    split4(K[src], h, l); gKh[i] = h; gKl[i] = l;
    split4(V[src], h, l); gVh[i] = h; gVl[i] = l;
}

// ---------------- mma / ldmatrix / cp.async helpers ----------------
__device__ __forceinline__ void ldsm4(uint32_t* r, uint32_t addr)
{
    asm volatile("ldmatrix.sync.aligned.m8n8.x4.shared.b16 {%0,%1,%2,%3},[%4];"
        : "=r"(r[0]), "=r"(r[1]), "=r"(r[2]), "=r"(r[3]) : "r"(addr));
}
__device__ __forceinline__ void ldsm4t(uint32_t* r, uint32_t addr)
{
    asm volatile("ldmatrix.sync.aligned.m8n8.x4.trans.shared.b16 {%0,%1,%2,%3},[%4];"
        : "=r"(r[0]), "=r"(r[1]), "=r"(r[2]), "=r"(r[3]) : "r"(addr));
}
__device__ __forceinline__ void mma16816(float* c, const uint32_t* a,
                                         uint32_t b0, uint32_t b1)
{
    asm volatile("mma.sync.aligned.m16n8k16.row.col.f32.bf16.bf16.f32 "
        "{%0,%1,%2,%3},{%4,%5,%6,%7},{%8,%9},{%0,%1,%2,%3};"
        : "+f"(c[0]), "+f"(c[1]), "+f"(c[2]), "+f"(c[3])
        : "r"(a[0]), "r"(a[1]), "r"(a[2]), "r"(a[3]), "r"(b0), "r"(b1));
}
__device__ __forceinline__ void cpa16(uint32_t dst, const void* src)
{
    asm volatile("cp.async.cg.shared.global [%0], [%1], 16;"
                 :: "r"(dst), "l"(src) : "memory");
}
__device__ __forceinline__ float ex2f(float x)
{
    float y;
    asm("ex2.approx.ftz.f32 %0, %1;" : "=f"(y) : "f"(x));
    return y;
}
#define CPA_COMMIT() asm volatile("cp.async.commit_group;" ::: "memory")
#define CPA_WAIT1()  asm volatile("cp.async.wait_group 1;" ::: "memory")

// ---------------- main attention kernel ----------------
__global__ void __launch_bounds__(NT, 2)
attn_fwd_kernel(const float4* __restrict__ Qg, float* __restrict__ Og)
{
    extern __shared__ char smem[];
    uint32_t sb;
    asm("{.reg .u64 t; cvta.to.shared.u64 t, %1; cvt.u32.u64 %0, t;}"
        : "=r"(sb) : "l"(smem));

    const int b    = blockIdx.y;
    const int m0   = blockIdx.x * BM;
    const int tid  = threadIdx.x;
    const int lane = tid & 31;
    const int warp = tid >> 5;    // 0..3
    const int b2048 = b * Ss;
    const int cnt  = g_cnt[b];
    const int ntiles = (cnt + BN - 1) / BN;

    const uint4* Kh4 = reinterpret_cast<const uint4*>(gKh);
    const uint4* Kl4 = reinterpret_cast<const uint4*>(gKl);
    const uint4* Vh4 = reinterpret_cast<const uint4*>(gVh);
    const uint4* Vl4 = reinterpret_cast<const uint4*>(gVl);

    // ---- prologue: issue K/V loads for tiles 0 and 1 (two cp.async groups) ----
    #pragma unroll
    for (int p = 0; p < 2; ++p) {
        uint32_t kb = sb + K_OFF + p * 16384u;
        uint32_t vb = sb + V_OFF + p * 16384u;
        #pragma unroll
        for (int it = 0; it < 4; ++it) {
            int gi = it * NT + tid;       // 0..511
            int row = gi >> 4, g = gi & 15;
            uint32_t sw16 = (uint32_t)(row * 16 + (g ^ (row & 7))) * 16u;
            size_t gidx = (size_t)(b2048 + p * BN + row) * 16 + g;
            cpa16(kb + sw16,         Kh4 + gidx);
            cpa16(kb + 8192 + sw16,  Kl4 + gidx);
            cpa16(vb + sw16,         Vh4 + gidx);
            cpa16(vb + 8192 + sw16,  Vl4 + gidx);
        }
        CPA_COMMIT();
    }

    // ---- stage Q: fp32 -> hi/lo bf16 split in-kernel (overlaps K/V loads) ----
    #pragma unroll
    for (int it = 0; it < 8; ++it) {
        int gi = it * NT + tid;           // 0..1023
        int row = gi >> 4, g = gi & 15;
        const float4* src = Qg + (size_t)(b2048 + m0 + row) * 32 + g * 2;
        float4 f0 = src[0], f1 = src[1];
        uint2 h0, l0, h1, l1;
        split4(f0, h0, l0);
        split4(f1, h1, l1);
        uint32_t sw16 = (uint32_t)(row * 16 + (g ^ (row & 7))) * 16u;
        *reinterpret_cast<uint4*>(smem + QH_OFF + sw16) = make_uint4(h0.x, h0.y, h1.x, h1.y);
        *reinterpret_cast<uint4*>(smem + QL_OFF + sw16) = make_uint4(l0.x, l0.y, l1.x, l1.y);
    }

    // per-thread ldmatrix address patterns
    const int arow = 16 * warp + (lane & 15);          // A-frag row (Q)
    const int ag   = lane >> 4;                        // granule 0/1
    const int brow = (lane & 7) + ((lane & 16) >> 1);  // B-frag (K) row
    const int bg   = (lane >> 3) & 1;
    const int vrl  = lane & 15;                        // V-frag row
    const int ct2  = (lane & 3) * 2;                   // col-pair offset
    const int gr   = lane >> 2;                        // row group

    float o[16][4];
    #pragma unroll
    for (int nt = 0; nt < 16; ++nt)
        #pragma unroll
        for (int c = 0; c < 4; ++c) o[nt][c] = 0.0f;
    float mst0 = -1e30f, mst1 = -1e30f, lsum0 = 0.0f, lsum1 = 0.0f;
    const float lsc = 0.08838834764831845f * 1.4426950408889634f; // 1/sqrt(d) * log2(e)

    for (int t = 0; t < ntiles; ++t) {
        const int n0 = t * BN;
        const uint32_t kbase = sb + K_OFF + (uint32_t)(t & 1) * 16384u;
        const uint32_t vbase = sb + V_OFF + (uint32_t)(t & 1) * 16384u;

        CPA_WAIT1();        // tile t's group landed (t+1 may stay in flight)
        __syncthreads();

        // ---- S = Q K^T (3-term bf16 split) ----
        float s[4][4];
        #pragma unroll
        for (int nt = 0; nt < 4; ++nt)
            #pragma unroll
            for (int c = 0; c < 4; ++c) s[nt][c] = 0.0f;

        #pragma unroll
        for (int kc = 0; kc < 8; ++kc) {
            uint32_t qh[4], ql[4];
            uint32_t qoff = (uint32_t)(arow * 256 + (((2 * kc + ag) ^ (arow & 7)) << 4));
            ldsm4(qh, sb + QH_OFF + qoff);
            ldsm4(ql, sb + QL_OFF + qoff);
            #pragma unroll
            for (int ntp = 0; ntp < 2; ++ntp) {
                uint32_t kh[4], kl[4];
                uint32_t koff = (uint32_t)((16 * ntp + brow) * 256 +
                                           (((2 * kc + bg) ^ (brow & 7)) << 4));
                ldsm4(kh, kbase + koff);
                ldsm4(kl, kbase + 8192 + koff);
                mma16816(s[2 * ntp],     qh, kh[0], kh[1]);
                mma16816(s[2 * ntp],     qh, kl[0], kl[1]);
                mma16816(s[2 * ntp],     ql, kh[0], kh[1]);
                mma16816(s[2 * ntp + 1], qh, kh[2], kh[3]);
                mma16816(s[2 * ntp + 1], qh, kl[2], kl[3]);
                mma16816(s[2 * ntp + 1], ql, kh[2], kh[3]);
            }
        }

        // ---- scale (log2 domain) + tail predicate + online softmax ----
        float tm0 = -1e30f, tm1 = -1e30f;
        #pragma unroll
        for (int nt = 0; nt < 4; ++nt) {
            int jb = n0 + 8 * nt + ct2;
            bool mx = jb >= cnt, my = (jb + 1) >= cnt;
            float v0 = s[nt][0] * lsc; if (mx) v0 = -1e30f;
            float v1 = s[nt][1] * lsc; if (my) v1 = -1e30f;
            float v2 = s[nt][2] * lsc; if (mx) v2 = -1e30f;
            float v3 = s[nt][3] * lsc; if (my) v3 = -1e30f;
            s[nt][0] = v0; s[nt][1] = v1; s[nt][2] = v2; s[nt][3] = v3;
            tm0 = fmaxf(tm0, fmaxf(v0, v1));
            tm1 = fmaxf(tm1, fmaxf(v2, v3));
        }
        tm0 = fmaxf(tm0, __shfl_xor_sync(0xffffffffu, tm0, 1));
        tm0 = fmaxf(tm0, __shfl_xor_sync(0xffffffffu, tm0, 2));
        tm1 = fmaxf(tm1, __shfl_xor_sync(0xffffffffu, tm1, 1));
        tm1 = fmaxf(tm1, __shfl_xor_sync(0xffffffffu, tm1, 2));

        float mn0 = fmaxf(mst0, tm0), mn1 = fmaxf(mst1, tm1);
        float al0 = ex2f(mst0 - mn0), al1 = ex2f(mst1 - mn1);
        mst0 = mn0; mst1 = mn1;

        uint32_t ph[4][2], pl[4][2];
        float ps0 = 0.0f, ps1 = 0.0f;
        #pragma unroll
        for (int nt = 0; nt < 4; ++nt) {
            float p0 = ex2f(s[nt][0] - mn0);
            float p1 = ex2f(s[nt][1] - mn0);
            float p2 = ex2f(s[nt][2] - mn1);
            float p3 = ex2f(s[nt][3] - mn1);
            ps0 += p0 + p1; ps1 += p2 + p3;
            __nv_bfloat162 h0 = __float22bfloat162_rn(make_float2(p0, p1));
            __nv_bfloat162 h1 = __float22bfloat162_rn(make_float2(p2, p3));
            float2 d0 = __bfloat1622float2(h0);
            float2 d1 = __bfloat1622float2(h1);
            __nv_bfloat162 l0 = __float22bfloat162_rn(make_float2(p0 - d0.x, p1 - d0.y));
            __nv_bfloat162 l1 = __float22bfloat162_rn(make_float2(p2 - d1.x, p3 - d1.y));
            ph[nt][0] = reinterpret_cast<uint32_t&>(h0);
            ph[nt][1] = reinterpret_cast<uint32_t&>(h1);
            pl[nt][0] = reinterpret_cast<uint32_t&>(l0);
            pl[nt][1] = reinterpret_cast<uint32_t&>(l1);
        }
        ps0 += __shfl_xor_sync(0xffffffffu, ps0, 1);
        ps0 += __shfl_xor_sync(0xffffffffu, ps0, 2);
        ps1 += __shfl_xor_sync(0xffffffffu, ps1, 1);
        ps1 += __shfl_xor_sync(0xffffffffu, ps1, 2);
        lsum0 = lsum0 * al0 + ps0;
        lsum1 = lsum1 * al1 + ps1;

        #pragma unroll
        for (int nt = 0; nt < 16; ++nt) {
            o[nt][0] *= al0; o[nt][1] *= al0;
            o[nt][2] *= al1; o[nt][3] *= al1;
        }

        // ---- O += P V (3-term split; P frags straight from registers) ----
        #pragma unroll
        for (int kc = 0; kc < 2; ++kc) {
            uint32_t ah[4] = {ph[2 * kc][0], ph[2 * kc][1],
                              ph[2 * kc + 1][0], ph[2 * kc + 1][1]};
            uint32_t al[4] = {pl[2 * kc][0], pl[2 * kc][1],
                              pl[2 * kc + 1][0], pl[2 * kc + 1][1]};
            #pragma unroll
            for (int ntp = 0; ntp < 8; ++ntp) {
                uint32_t vh[4], vl[4];
                uint32_t voff = (uint32_t)((16 * kc + vrl) * 256 +
                                           (((2 * ntp + ag) ^ (vrl & 7)) << 4));
                ldsm4t(vh, vbase + voff);
                ldsm4t(vl, vbase + 8192 + voff);
                mma16816(o[2 * ntp],     ah, vh[0], vh[1]);
                mma16816(o[2 * ntp],     ah, vl[0], vl[1]);
                mma16816(o[2 * ntp],     al, vh[0], vh[1]);
                mma16816(o[2 * ntp + 1], ah, vh[2], vh[3]);
                mma16816(o[2 * ntp + 1], ah, vl[2], vl[3]);
                mma16816(o[2 * ntp + 1], al, vh[2], vh[3]);
            }
        }
        __syncthreads();    // buffer (t&1) fully consumed

        // ---- issue K/V loads for tile t+2 into the freed buffer ----
        int tt = t + 2;
        if (tt < ntiles) {
            uint32_t kb = sb + K_OFF + (uint32_t)(tt & 1) * 16384u;
            uint32_t vb = sb + V_OFF + (uint32_t)(tt & 1) * 16384u;
            #pragma unroll
            for (int it = 0; it < 4; ++it) {
                int gi = it * NT + tid;
                int row = gi >> 4, g = gi & 15;
                uint32_t sw16 = (uint32_t)(row * 16 + (g ^ (row & 7))) * 16u;
                size_t gidx = (size_t)(b2048 + tt * BN + row) * 16 + g;
                cpa16(kb + sw16,        Kh4 + gidx);
                cpa16(kb + 8192 + sw16, Kl4 + gidx);
                cpa16(vb + sw16,        Vh4 + gidx);
                cpa16(vb + 8192 + sw16, Vl4 + gidx);
            }
        }
        CPA_COMMIT();        // commit (possibly empty) group to keep accounting
    }

    // ---- epilogue ----
    float il0 = 1.0f / lsum0, il1 = 1.0f / lsum1;
    int r0 = m0 + 16 * warp + gr;
    float* O0 = Og + ((size_t)b2048 + r0) * Dd + ct2;
    float* O1 = O0 + 8 * Dd;
    #pragma unroll
    for (int nt = 0; nt < 16; ++nt) {
        *reinterpret_cast<float2*>(O0 + 8 * nt) =
            make_float2(o[nt][0] * il0, o[nt][1] * il0);
        *reinterpret_cast<float2*>(O1 + 8 * nt) =
            make_float2(o[nt][2] * il1, o[nt][3] * il1);
    }
}

extern "C" void kernel_launch(void* const* d_in, const int* in_sizes, int n_in,
                              void* d_out, int out_size)
{
    const float* q = (const float*)d_in[0];
    const float* k = (const float*)d_in[1];
    const float* v = (const float*)d_in[2];
    const void*  m = d_in[3];
    float* out = (float*)d_out;

    mask_prep_kernel<<<Bb, 256>>>(m);
    kv_prep_kernel<<<(N4 + 255) / 256, 256>>>(
        (const float4*)k, (const float4*)v);

    cudaFuncSetAttribute(attn_fwd_kernel,
                         cudaFuncAttributeMaxDynamicSharedMemorySize, SMEM_BYTES);
    dim3 grid(Ss / BM, Bb);
    attn_fwd_kernel<<<grid, NT, SMEM_BYTES>>>((const float4*)q, out);
}